// round 2
// baseline (speedup 1.0000x reference)
#include <cuda_runtime.h>
#include <math.h>

// Problem dims
#define BSZ   4
#define LSEQ  8192
#define DIN   512
#define DGATE 2048
#define DHID  128
#define DST   512
#define TCH   128
#define CCH   64
#define MROWS (BSZ*LSEQ)   // 32768

// ---------------- scratch (static device globals; no runtime alloc) --------
__device__ float g_xn  [(size_t)MROWS*DIN];          // 67 MB
__device__ float g_v   [(size_t)MROWS*DGATE];        // 268 MB
__device__ float g_un  [(size_t)MROWS*DHID];         // 16.8 MB
__device__ float g_unT [(size_t)BSZ*DHID*LSEQ];      // 16.8 MB
__device__ float g_y   [(size_t)MROWS*DHID];         // 16.8 MB
__device__ float g_Zre [(size_t)BSZ*CCH*DHID*DST];   // 67 MB (reused as P_re)
__device__ float g_Zim [(size_t)BSZ*CCH*DHID*DST];   // 67 MB (reused as P_im)
__device__ float g_ArevT_re[DST*TCH];
__device__ float g_ArevT_im[DST*TCH];
__device__ float g_Ahat_re [TCH*DST];
__device__ float g_Ahat_im [TCH*DST];
__device__ float g_abar_re [DST];
__device__ float g_abar_im [DST];
__device__ float g_cre     [DHID*DST];
__device__ float g_cim     [DHID*DST];
__device__ float g_kc      [TCH*DHID];

// ---------------- helpers ---------------------------------------------------
__device__ __forceinline__ float gelu_exact(float x) {
    return 0.5f * x * (1.0f + erff(x * 0.70710678118654752440f));
}

// ---------------- generic batched 128x128 SGEMM  C = A(MxK) * B(NxK)^T ------
// Both operands K-contiguous (row-major with leading dims lda/ldb).
// grid: (N/128, M/128, nbatch).  Batch z decomposes as zb=z/CB, zc=z%CB with
// separate strides so non-uniform (b,c) offsets work.
enum { EPI_STORE = 0, EPI_GELU = 1, EPI_MUL = 2, EPI_SUB = 3, EPI_FINAL = 4 };

template <int EPI>
__global__ __launch_bounds__(256)
void sgemm(int K,
           const float* __restrict__ A, int lda, long long sAb, long long sAc,
           const float* __restrict__ Bm, int ldb, long long sBb, long long sBc,
           float* __restrict__ C, int ldc, long long sCb, long long sCc,
           int CB,
           const float* __restrict__ bias, const float* __restrict__ resid)
{
    __shared__ float As[16][128];
    __shared__ float Bs[16][128];

    const int zb = blockIdx.z / CB, zc = blockIdx.z % CB;
    A  += (size_t)zb * sAb + (size_t)zc * sAc;
    Bm += (size_t)zb * sBb + (size_t)zc * sBc;
    C  += (size_t)zb * sCb + (size_t)zc * sCc;

    const int tid  = threadIdx.x;
    const int row0 = blockIdx.y * 128;
    const int col0 = blockIdx.x * 128;

    // loader mapping: 512 float4 slots per 128x16 tile, 2 slots/thread
    const int s0    = tid * 2;
    const int lrow0 = s0 >> 2,      lk0 = (s0 & 3) * 4;
    const int lrow1 = (s0 + 1) >> 2, lk1 = ((s0 + 1) & 3) * 4;

    const int tm = (tid >> 4) * 8;
    const int tn = (tid & 15) * 8;

    float acc[8][8];
#pragma unroll
    for (int i = 0; i < 8; i++)
#pragma unroll
        for (int j = 0; j < 8; j++) acc[i][j] = 0.f;

    for (int k0 = 0; k0 < K; k0 += 16) {
        float4 a0 = *(const float4*)(A  + (size_t)(row0 + lrow0) * lda + k0 + lk0);
        float4 a1 = *(const float4*)(A  + (size_t)(row0 + lrow1) * lda + k0 + lk1);
        float4 b0 = *(const float4*)(Bm + (size_t)(col0 + lrow0) * ldb + k0 + lk0);
        float4 b1 = *(const float4*)(Bm + (size_t)(col0 + lrow1) * ldb + k0 + lk1);
        __syncthreads();
        As[lk0 + 0][lrow0] = a0.x; As[lk0 + 1][lrow0] = a0.y;
        As[lk0 + 2][lrow0] = a0.z; As[lk0 + 3][lrow0] = a0.w;
        As[lk1 + 0][lrow1] = a1.x; As[lk1 + 1][lrow1] = a1.y;
        As[lk1 + 2][lrow1] = a1.z; As[lk1 + 3][lrow1] = a1.w;
        Bs[lk0 + 0][lrow0] = b0.x; Bs[lk0 + 1][lrow0] = b0.y;
        Bs[lk0 + 2][lrow0] = b0.z; Bs[lk0 + 3][lrow0] = b0.w;
        Bs[lk1 + 0][lrow1] = b1.x; Bs[lk1 + 1][lrow1] = b1.y;
        Bs[lk1 + 2][lrow1] = b1.z; Bs[lk1 + 3][lrow1] = b1.w;
        __syncthreads();
#pragma unroll
        for (int kk = 0; kk < 16; kk++) {
            float4 av0 = *(const float4*)&As[kk][tm];
            float4 av1 = *(const float4*)&As[kk][tm + 4];
            float4 bv0 = *(const float4*)&Bs[kk][tn];
            float4 bv1 = *(const float4*)&Bs[kk][tn + 4];
            float ar[8] = {av0.x, av0.y, av0.z, av0.w, av1.x, av1.y, av1.z, av1.w};
            float br[8] = {bv0.x, bv0.y, bv0.z, bv0.w, bv1.x, bv1.y, bv1.z, bv1.w};
#pragma unroll
            for (int i = 0; i < 8; i++)
#pragma unroll
                for (int j = 0; j < 8; j++)
                    acc[i][j] = fmaf(ar[i], br[j], acc[i][j]);
        }
    }

#pragma unroll
    for (int i = 0; i < 8; i++) {
        const int r = row0 + tm + i;
#pragma unroll
        for (int j = 0; j < 8; j++) {
            const int cc  = col0 + tn + j;
            const size_t idx = (size_t)r * ldc + cc;
            float val = acc[i][j];
            if (EPI == EPI_GELU)       val = gelu_exact(val);
            else if (EPI == EPI_MUL)   val = val * C[idx];
            else if (EPI == EPI_SUB)   val = C[idx] - val;
            else if (EPI == EPI_FINAL) val = val + bias[cc] + resid[idx];
            C[idx] = val;
        }
    }
}

// ---------------- layernorm over 512 (one block per row) --------------------
__global__ void ln512(const float* __restrict__ x, const float* __restrict__ g,
                      const float* __restrict__ b, float* __restrict__ out)
{
    const int row = blockIdx.x, tid = threadIdx.x;  // 128 threads
    float4 v = ((const float4*)(x + (size_t)row * 512))[tid];
    float s  = v.x + v.y + v.z + v.w;
    float sq = v.x * v.x + v.y * v.y + v.z * v.z + v.w * v.w;
#pragma unroll
    for (int o = 16; o; o >>= 1) {
        s  += __shfl_xor_sync(0xffffffffu, s, o);
        sq += __shfl_xor_sync(0xffffffffu, sq, o);
    }
    __shared__ float ss[4], ssq[4];
    if ((tid & 31) == 0) { ss[tid >> 5] = s; ssq[tid >> 5] = sq; }
    __syncthreads();
    s  = ss[0] + ss[1] + ss[2] + ss[3];
    sq = ssq[0] + ssq[1] + ssq[2] + ssq[3];
    const float mean = s * (1.f / 512.f);
    const float var  = sq * (1.f / 512.f) - mean * mean;
    const float rs   = rsqrtf(var + 1e-5f);
    float4 gv = ((const float4*)g)[tid], bv = ((const float4*)b)[tid];
    float4 o4;
    o4.x = (v.x - mean) * rs * gv.x + bv.x;
    o4.y = (v.y - mean) * rs * gv.y + bv.y;
    o4.z = (v.z - mean) * rs * gv.z + bv.z;
    o4.w = (v.w - mean) * rs * gv.w + bv.w;
    ((float4*)(out + (size_t)row * 512))[tid] = o4;
}

// ---------------- layernorm over 128, in place; also writes transposed copy -
__global__ void ln128(float* __restrict__ u, float* __restrict__ uT,
                      const float* __restrict__ g, const float* __restrict__ b)
{
    const int warp = threadIdx.x >> 5, lane = threadIdx.x & 31;
    const int row  = blockIdx.x * 8 + warp;   // 4096 blocks x 8 warps
    float4 v = ((const float4*)(u + (size_t)row * 128))[lane];
    float s  = v.x + v.y + v.z + v.w;
    float sq = v.x * v.x + v.y * v.y + v.z * v.z + v.w * v.w;
#pragma unroll
    for (int o = 16; o; o >>= 1) {
        s  += __shfl_xor_sync(0xffffffffu, s, o);
        sq += __shfl_xor_sync(0xffffffffu, sq, o);
    }
    const float mean = s * (1.f / 128.f);
    const float var  = sq * (1.f / 128.f) - mean * mean;
    const float rs   = rsqrtf(var + 1e-5f);
    float4 gv = ((const float4*)g)[lane], bv = ((const float4*)b)[lane];
    float4 o4;
    o4.x = (v.x - mean) * rs * gv.x + bv.x;
    o4.y = (v.y - mean) * rs * gv.y + bv.y;
    o4.z = (v.z - mean) * rs * gv.z + bv.z;
    o4.w = (v.w - mean) * rs * gv.w + bv.w;
    ((float4*)(u + (size_t)row * 128))[lane] = o4;
    const int bb = row >> 13, l = row & 8191;
    float* base = uT + (size_t)bb * 128 * 8192 + l;
    const int h = lane * 4;
    base[(size_t)(h + 0) * 8192] = o4.x;
    base[(size_t)(h + 1) * 8192] = o4.y;
    base[(size_t)(h + 2) * 8192] = o4.z;
    base[(size_t)(h + 3) * 8192] = o4.w;
}

// ---------------- DSS tables -------------------------------------------------
// lam = -exp(lam_re) + i exp(lam_im);  a = exp(lam);  c = (C_re+iC_im)(a-1)/lam
__global__ void dss_tables(const float* __restrict__ lam_re, const float* __restrict__ lam_im,
                           const float* __restrict__ C_re, const float* __restrict__ C_im,
                           float* __restrict__ ArevT_re, float* __restrict__ ArevT_im,
                           float* __restrict__ Ahat_re, float* __restrict__ Ahat_im,
                           float* __restrict__ abar_re, float* __restrict__ abar_im,
                           float* __restrict__ cre, float* __restrict__ cim)
{
    const int n = blockIdx.x * 128 + threadIdx.x;
    if (n >= DST) return;
    const float lre = -expf(lam_re[n]);
    const float lim =  expf(lam_im[n]);
    const float mag = expf(lre);
    const float er = mag * cosf(lim), ei = mag * sinf(lim);
    const float den = lre * lre + lim * lim;
    const float nr = er - 1.f, ni = ei;
    const float wr = (nr * lre + ni * lim) / den;
    const float wi = (ni * lre - nr * lim) / den;
    for (int h = 0; h < DHID; h++) {
        const float a = C_re[h * DST + n], b = C_im[h * DST + n];
        cre[h * DST + n] = a * wr - b * wi;
        cim[h * DST + n] = a * wi + b * wr;
    }
    for (int t = 0; t < TCH; t++) {
        const float x1 = (float)(TCH - 1 - t);
        const float m1 = expf(x1 * lre);
        ArevT_re[n * TCH + t] = m1 * cosf(x1 * lim);
        ArevT_im[n * TCH + t] = m1 * sinf(x1 * lim);
        const float x2 = (float)(t + 1);
        const float m2 = expf(x2 * lre);
        Ahat_re[t * DST + n] = m2 * cosf(x2 * lim);
        Ahat_im[t * DST + n] = m2 * sinf(x2 * lim);
    }
    const float m3 = expf((float)TCH * lre);
    abar_re[n] = m3 * cosf((float)TCH * lim);
    abar_im[n] = m3 * sinf((float)TCH * lim);
}

// kern_chunk[d,h] = Re( sum_n c[h,n] exp(d*lam_n) ),  d in [0,128)
__global__ void kernchunk(const float* __restrict__ lam_re, const float* __restrict__ lam_im,
                          const float* __restrict__ cre, const float* __restrict__ cim,
                          float* __restrict__ kc)
{
    const int d = blockIdx.x, h = threadIdx.x;   // <<<128,128>>>
    __shared__ float er[DST], ei[DST];
    for (int n = h; n < DST; n += 128) {
        const float lre = -expf(lam_re[n]);
        const float lim =  expf(lam_im[n]);
        const float m = expf((float)d * lre);
        er[n] = m * cosf((float)d * lim);
        ei[n] = m * sinf((float)d * lim);
    }
    __syncthreads();
    float s = 0.f;
    for (int n = 0; n < DST; n++)
        s += cre[h * DST + n] * er[n] - cim[h * DST + n] * ei[n];
    kc[d * DHID + h] = s;
}

// ---------------- chunk scan: S <- abar*S + Z; emits P = c * S_start --------
// One lane per (b, h, n): 4*128*512 = 262,144 lanes; iterates CCH internally.
__global__ void scan_kernel(float* __restrict__ Zre, float* __restrict__ Zim,
                            const float* __restrict__ cre, const float* __restrict__ cim,
                            const float* __restrict__ abr, const float* __restrict__ abi)
{
    const int t = blockIdx.x * 256 + threadIdx.x;   // [0, 262144)
    const int n = t & 511, h = (t >> 9) & 127, b = t >> 16;
    const float ar = abr[n], ai = abi[n];
    const float kr = cre[h * DST + n], ki = cim[h * DST + n];
    float Sr = 0.f, Si = 0.f;
    const size_t stride = (size_t)DHID * DST;
    size_t idx = ((size_t)b * CCH * DHID + h) * DST + n;
    for (int c = 0; c < CCH; c++) {
        const float zr = Zre[idx], zi = Zim[idx];
        Zre[idx] = kr * Sr - ki * Si;   // P_re (uses state BEFORE this chunk)
        Zim[idx] = kr * Si + ki * Sr;   // P_im
        const float t1 = ar * Sr - ai * Si + zr;
        Si = ar * Si + ai * Sr + zi;
        Sr = t1;
        idx += stride;
    }
}

// ---------------- intra-chunk triangular conv + skip residual ---------------
__global__ void intra_kernel(const float* __restrict__ un, const float* __restrict__ kc,
                             float* __restrict__ y, const float* __restrict__ Ds)
{
    extern __shared__ float sm[];
    float* Uc = sm;                  // 128x128
    float* Kc = sm + TCH * DHID;     // 128x128
    const size_t base = (size_t)blockIdx.x * TCH * DHID;
    for (int i = threadIdx.x; i < TCH * DHID / 4; i += 256) {
        ((float4*)Uc)[i] = ((const float4*)(un + base))[i];
        ((float4*)Kc)[i] = ((const float4*)kc)[i];
    }
    __syncthreads();
    for (int e = threadIdx.x; e < TCH * DHID; e += 256) {
        const int dt = e >> 7, h = e & 127;
        float s = Uc[dt * DHID + h] * Ds[h];
        for (int j = 0; j <= dt; j++)
            s = fmaf(Kc[(dt - j) * DHID + h], Uc[j * DHID + h], s);
        y[base + e] += s;
    }
}

// ---------------- launch ----------------------------------------------------
extern "C" void kernel_launch(void* const* d_in, const int* in_sizes, int n_in,
                              void* d_out, int out_size)
{
    const float* x      = (const float*)d_in[0];
    const float* norm_g = (const float*)d_in[1];
    const float* norm_b = (const float*)d_in[2];
    const float* W_v    = (const float*)d_in[3];
    const float* W_u    = (const float*)d_in[4];
    const float* W_uc   = (const float*)d_in[5];
    const float* W_o    = (const float*)d_in[6];
    const float* b_o    = (const float*)d_in[7];
    const float* dss_g  = (const float*)d_in[8];
    const float* dss_b  = (const float*)d_in[9];
    const float* lam_re = (const float*)d_in[10];
    const float* lam_im = (const float*)d_in[11];
    const float* C_re   = (const float*)d_in[12];
    const float* C_im   = (const float*)d_in[13];
    const float* D_skip = (const float*)d_in[14];
    float* out = (float*)d_out;

    float *xn, *v, *un, *unT, *y, *Zre, *Zim;
    float *ArT_re, *ArT_im, *Ah_re, *Ah_im, *abr, *abi, *cre, *cim, *kc;
    cudaGetSymbolAddress((void**)&xn,  g_xn);
    cudaGetSymbolAddress((void**)&v,   g_v);
    cudaGetSymbolAddress((void**)&un,  g_un);
    cudaGetSymbolAddress((void**)&unT, g_unT);
    cudaGetSymbolAddress((void**)&y,   g_y);
    cudaGetSymbolAddress((void**)&Zre, g_Zre);
    cudaGetSymbolAddress((void**)&Zim, g_Zim);
    cudaGetSymbolAddress((void**)&ArT_re, g_ArevT_re);
    cudaGetSymbolAddress((void**)&ArT_im, g_ArevT_im);
    cudaGetSymbolAddress((void**)&Ah_re,  g_Ahat_re);
    cudaGetSymbolAddress((void**)&Ah_im,  g_Ahat_im);
    cudaGetSymbolAddress((void**)&abr, g_abar_re);
    cudaGetSymbolAddress((void**)&abi, g_abar_im);
    cudaGetSymbolAddress((void**)&cre, g_cre);
    cudaGetSymbolAddress((void**)&cim, g_cim);
    cudaGetSymbolAddress((void**)&kc,  g_kc);

    // 1) xn = LN(x)
    ln512<<<MROWS, 128>>>(x, norm_g, norm_b, xn);

    // 2) v = gelu(xn @ W_v^T)   [32768 x 2048]
    sgemm<EPI_GELU><<<dim3(DGATE / 128, MROWS / 128, 1), 256>>>(
        DIN, xn, DIN, 0, 0, W_v, DIN, 0, 0, v, DGATE, 0, 0, 1, nullptr, nullptr);

    // 3) u = gelu(xn @ W_u^T)   [32768 x 128]
    sgemm<EPI_GELU><<<dim3(1, MROWS / 128, 1), 256>>>(
        DIN, xn, DIN, 0, 0, W_u, DIN, 0, 0, un, DHID, 0, 0, 1, nullptr, nullptr);

    // 4) un = LN(u); also transposed copy unT[b,h,l]
    ln128<<<MROWS / 8, 256>>>(un, unT, dss_g, dss_b);

    // 5) DSS tables
    dss_tables<<<DST / 128, 128>>>(lam_re, lam_im, C_re, C_im,
                                   ArT_re, ArT_im, Ah_re, Ah_im, abr, abi, cre, cim);
    kernchunk<<<TCH, DHID>>>(lam_re, lam_im, cre, cim, kc);

    // 6) Z[b,c,h,n] = sum_t un[b,cT+t,h] * a_n^{T-1-t}   (batched GEMM, re & im)
    sgemm<EPI_STORE><<<dim3(DST / 128, 1, BSZ * CCH), 256>>>(
        TCH,
        unT, LSEQ, (long long)DHID * LSEQ, TCH,
        ArT_re, TCH, 0, 0,
        Zre, DST, (long long)CCH * DHID * DST, (long long)DHID * DST,
        CCH, nullptr, nullptr);
    sgemm<EPI_STORE><<<dim3(DST / 128, 1, BSZ * CCH), 256>>>(
        TCH,
        unT, LSEQ, (long long)DHID * LSEQ, TCH,
        ArT_im, TCH, 0, 0,
        Zim, DST, (long long)CCH * DHID * DST, (long long)DHID * DST,
        CCH, nullptr, nullptr);

    // 7) scan across chunks, P = c * S_start written in place over Z
    //    grid = B*H*N / 256 = 1024 blocks (scan iterates CCH internally)
    scan_kernel<<<(BSZ * DHID * DST) / 256, 256>>>(Zre, Zim, cre, cim, abr, abi);

    // 8) y_inter = Ahat_re @ P_re - Ahat_im @ P_im   (batched GEMMs)
    sgemm<EPI_STORE><<<dim3(1, 1, BSZ * CCH), 256>>>(
        DST,
        Ah_re, DST, 0, 0,
        Zre, DST, (long long)CCH * DHID * DST, (long long)DHID * DST,
        y, DHID, (long long)CCH * TCH * DHID, (long long)TCH * DHID,
        CCH, nullptr, nullptr);
    sgemm<EPI_SUB><<<dim3(1, 1, BSZ * CCH), 256>>>(
        DST,
        Ah_im, DST, 0, 0,
        Zim, DST, (long long)CCH * DHID * DST, (long long)DHID * DST,
        y, DHID, (long long)CCH * TCH * DHID, (long long)TCH * DHID,
        CCH, nullptr, nullptr);

    // 9) y += intra-chunk conv + un * D_skip
    cudaFuncSetAttribute(intra_kernel, cudaFuncAttributeMaxDynamicSharedMemorySize,
                         2 * TCH * DHID * (int)sizeof(float));
    intra_kernel<<<BSZ * CCH, 256, 2 * TCH * DHID * sizeof(float)>>>(un, kc, y, D_skip);

    // 10) gv = (y @ W_uc^T) * v   (in place over v)
    sgemm<EPI_MUL><<<dim3(DGATE / 128, MROWS / 128, 1), 256>>>(
        DHID, y, DHID, 0, 0, W_uc, DHID, 0, 0, v, DGATE, 0, 0, 1, nullptr, nullptr);

    // 11) out = gv @ W_o^T + b_o + x
    sgemm<EPI_FINAL><<<dim3(DIN / 128, MROWS / 128, 1), 256>>>(
        DGATE, v, DGATE, 0, 0, W_o, DGATE, 0, 0, out, DIN, 0, 0, 1, b_o, x);
}

// round 4
// speedup vs baseline: 1.6093x; 1.6093x over previous
#include <cuda_runtime.h>
#include <cuda_bf16.h>
#include <cstdint>
#include <math.h>

// Problem dims
#define BSZ   4
#define LSEQ  8192
#define DIN   512
#define DGATE 2048
#define DHID  128
#define DST   512
#define TCH   128
#define CCH   64
#define MROWS (BSZ*LSEQ)   // 32768

// ---------------- scratch (static device globals; no runtime alloc) --------
__device__ float g_xn  [(size_t)MROWS*DIN];
__device__ float g_v   [(size_t)MROWS*DGATE];
__device__ float g_un  [(size_t)MROWS*DHID];
__device__ float g_unT [(size_t)BSZ*DHID*LSEQ];
__device__ float g_y   [(size_t)MROWS*DHID];
__device__ float g_Zre [(size_t)BSZ*CCH*DHID*DST];
__device__ float g_Zim [(size_t)BSZ*CCH*DHID*DST];
__device__ float g_ArevT_re[DST*TCH];
__device__ float g_ArevT_im[DST*TCH];
__device__ float g_Ahat_re [TCH*DST];
__device__ float g_Ahat_im [TCH*DST];
__device__ float g_abar_re [DST];
__device__ float g_abar_im [DST];
__device__ float g_cre     [DHID*DST];
__device__ float g_cim     [DHID*DST];
__device__ float g_kc      [TCH*DHID];

// ---------------- helpers ---------------------------------------------------
__device__ __forceinline__ float gelu_exact(float x) {
    return 0.5f * x * (1.0f + erff(x * 0.70710678118654752440f));
}
__device__ __forceinline__ uint32_t smem_u32(const void* p) {
    uint32_t a;
    asm("{ .reg .u64 t; cvta.to.shared.u64 t, %1; cvt.u32.u64 %0, t; }"
        : "=r"(a) : "l"(p));
    return a;
}
__device__ __forceinline__ void ldm_x4(uint32_t* r, uint32_t addr) {
    asm volatile("ldmatrix.sync.aligned.m8n8.x4.shared.b16 {%0,%1,%2,%3}, [%4];"
        : "=r"(r[0]), "=r"(r[1]), "=r"(r[2]), "=r"(r[3]) : "r"(addr));
}
__device__ __forceinline__ void mma_bf16(float* d, const uint32_t* a, const uint32_t* b) {
    asm volatile(
        "mma.sync.aligned.m16n8k16.row.col.f32.bf16.bf16.f32 "
        "{%0,%1,%2,%3}, {%4,%5,%6,%7}, {%8,%9}, {%0,%1,%2,%3};"
        : "+f"(d[0]), "+f"(d[1]), "+f"(d[2]), "+f"(d[3])
        : "r"(a[0]), "r"(a[1]), "r"(a[2]), "r"(a[3]), "r"(b[0]), "r"(b[1]));
}

enum { EPI_STORE = 0, EPI_GELU = 1, EPI_MUL = 2, EPI_SUB = 3, EPI_FINAL = 4 };

// smem: four 128-row buffers, 80B row stride (32 bf16 data + 16B pad)
#define ROWB    80
#define BUFB    (128 * ROWB)     // 10240
#define OFF_AHI 0
#define OFF_ALO (1 * BUFB)
#define OFF_BHI (2 * BUFB)
#define OFF_BLO (3 * BUFB)
#define TG_SMEM (4 * BUFB)       // 40960 bytes (< 48KB default)

// ---------------- split-bf16 HMMA GEMM  C = A(MxK) * B(NxK)^T ---------------
// 128x128 CTA tile, 8 warps (warp tile 32x64), K chunks of 32.
// fp32 inputs split to bf16 hi/lo in smem; acc = Ahi*Bhi + Ahi*Blo + Alo*Bhi.
template <int EPI>
__global__ __launch_bounds__(256)
void tgemm(int K,
           const float* __restrict__ A, int lda, long long sAb, long long sAc,
           const float* __restrict__ Bm, int ldb, long long sBb, long long sBc,
           float* __restrict__ C, int ldc, long long sCb, long long sCc,
           int CB,
           const float* __restrict__ bias, const float* __restrict__ resid)
{
    __shared__ __align__(16) char smem[TG_SMEM];
    const uint32_t sbase = smem_u32(smem);

    const int tid  = threadIdx.x;
    const int wid  = tid >> 5;
    const int lane = tid & 31;
    const int wm   = wid & 3;     // 4 warps along M
    const int wn   = wid >> 2;    // 2 warps along N

    const int zb = blockIdx.z / CB, zc = blockIdx.z % CB;
    A  += (size_t)zb * sAb + (size_t)zc * sAc;
    Bm += (size_t)zb * sBb + (size_t)zc * sBc;
    C  += (size_t)zb * sCb + (size_t)zc * sCc;
    const int row0 = blockIdx.y * 128;
    const int col0 = blockIdx.x * 128;

    float acc[2][8][4];
#pragma unroll
    for (int i = 0; i < 2; i++)
#pragma unroll
        for (int j = 0; j < 8; j++)
#pragma unroll
            for (int k = 0; k < 4; k++) acc[i][j][k] = 0.f;

    // precomputed ldmatrix smem addresses (constant across chunks)
    const uint32_t aRow = wm * 32 + (lane & 15);
    const uint32_t aCol = (lane & 16) ? 16u : 0u;
    const uint32_t aAddrHi = sbase + OFF_AHI + aRow * ROWB + aCol;
    const uint32_t bRow0 = wn * 64 + (lane & 7) + ((lane & 16) ? 8 : 0);
    const uint32_t bCol  = (lane & 8) ? 16u : 0u;
    const uint32_t bAddrHi = sbase + OFF_BHI + bRow0 * ROWB + bCol;

    const int nchunk = K >> 5;
    for (int c = 0; c < nchunk; c++) {
        const int k0 = c << 5;
        // ---- load 128x32 fp32 A and B tiles, split to bf16 hi/lo in smem ----
#pragma unroll
        for (int i = 0; i < 8; i++) {
            const int fidx = i * 256 + tid;          // 0..2047
            const bool isA = (i < 4);
            const int lrow = (fidx >> 3) & 127;
            const int c4   = fidx & 7;
            const float* src = isA
                ? (A  + (size_t)(row0 + lrow) * lda + k0 + c4 * 4)
                : (Bm + (size_t)(col0 + lrow) * ldb + k0 + c4 * 4);
            const float4 v = *(const float4*)src;
            __nv_bfloat162 h01 = __floats2bfloat162_rn(v.x, v.y);
            __nv_bfloat162 h23 = __floats2bfloat162_rn(v.z, v.w);
            const float l0 = v.x - __bfloat162float(h01.x);
            const float l1 = v.y - __bfloat162float(h01.y);
            const float l2 = v.z - __bfloat162float(h23.x);
            const float l3 = v.w - __bfloat162float(h23.y);
            __nv_bfloat162 q01 = __floats2bfloat162_rn(l0, l1);
            __nv_bfloat162 q23 = __floats2bfloat162_rn(l2, l3);
            uint2 hv, lv;
            hv.x = *(const uint32_t*)&h01; hv.y = *(const uint32_t*)&h23;
            lv.x = *(const uint32_t*)&q01; lv.y = *(const uint32_t*)&q23;
            const uint32_t off = lrow * ROWB + c4 * 8;
            *(uint2*)(smem + (isA ? OFF_AHI : OFF_BHI) + off) = hv;
            *(uint2*)(smem + (isA ? OFF_ALO : OFF_BLO) + off) = lv;
        }
        __syncthreads();

        // ---- compute: 2 k16 steps ----
#pragma unroll
        for (int k16 = 0; k16 < 2; k16++) {
            uint32_t ahi[2][4], alo[2][4];
#pragma unroll
            for (int mt = 0; mt < 2; mt++) {
                const uint32_t aa = aAddrHi + mt * (16 * ROWB) + k16 * 32;
                ldm_x4(ahi[mt], aa);
                ldm_x4(alo[mt], aa + (OFF_ALO - OFF_AHI));
            }
#pragma unroll
            for (int p = 0; p < 4; p++) {
                const uint32_t ba = bAddrHi + p * (16 * ROWB) + k16 * 32;
                uint32_t bhi[4], blo[4];
                ldm_x4(bhi, ba);
                ldm_x4(blo, ba + (OFF_BLO - OFF_BHI));
#pragma unroll
                for (int mt = 0; mt < 2; mt++) {
#pragma unroll
                    for (int hh = 0; hh < 2; hh++) {
                        float* d = acc[mt][p * 2 + hh];
                        mma_bf16(d, ahi[mt], &bhi[hh * 2]);
                        mma_bf16(d, ahi[mt], &blo[hh * 2]);
                        mma_bf16(d, alo[mt], &bhi[hh * 2]);
                    }
                }
            }
        }
        __syncthreads();
    }

    // ---- epilogue ----
    const int qrow = lane >> 2, qcol = (lane & 3) * 2;
#pragma unroll
    for (int mt = 0; mt < 2; mt++) {
#pragma unroll
        for (int nt = 0; nt < 8; nt++) {
            const int r0r = row0 + wm * 32 + mt * 16 + qrow;
            const int cc  = col0 + wn * 64 + nt * 8 + qcol;
            float* d = acc[mt][nt];
#pragma unroll
            for (int h = 0; h < 2; h++) {
                const int rr = r0r + h * 8;
                float2 o = make_float2(d[h * 2 + 0], d[h * 2 + 1]);
                float* p = C + (size_t)rr * ldc + cc;
                if (EPI == EPI_GELU) {
                    o.x = gelu_exact(o.x); o.y = gelu_exact(o.y);
                } else if (EPI == EPI_MUL) {
                    const float2 q = *(const float2*)p;
                    o.x *= q.x; o.y *= q.y;
                } else if (EPI == EPI_SUB) {
                    const float2 q = *(const float2*)p;
                    o.x = q.x - o.x; o.y = q.y - o.y;
                } else if (EPI == EPI_FINAL) {
                    const float2 bb = *(const float2*)(bias + cc);
                    const float2 rr2 = *(const float2*)(resid + (size_t)rr * ldc + cc);
                    o.x += bb.x + rr2.x; o.y += bb.y + rr2.y;
                }
                *(float2*)p = o;
            }
        }
    }
}

// ---------------- layernorm over 512 ----------------------------------------
__global__ void ln512(const float* __restrict__ x, const float* __restrict__ g,
                      const float* __restrict__ b, float* __restrict__ out)
{
    const int row = blockIdx.x, tid = threadIdx.x;  // 128 threads
    float4 v = ((const float4*)(x + (size_t)row * 512))[tid];
    float s  = v.x + v.y + v.z + v.w;
    float sq = v.x * v.x + v.y * v.y + v.z * v.z + v.w * v.w;
#pragma unroll
    for (int o = 16; o; o >>= 1) {
        s  += __shfl_xor_sync(0xffffffffu, s, o);
        sq += __shfl_xor_sync(0xffffffffu, sq, o);
    }
    __shared__ float ss[4], ssq[4];
    if ((tid & 31) == 0) { ss[tid >> 5] = s; ssq[tid >> 5] = sq; }
    __syncthreads();
    s  = ss[0] + ss[1] + ss[2] + ss[3];
    sq = ssq[0] + ssq[1] + ssq[2] + ssq[3];
    const float mean = s * (1.f / 512.f);
    const float var  = sq * (1.f / 512.f) - mean * mean;
    const float rs   = rsqrtf(var + 1e-5f);
    float4 gv = ((const float4*)g)[tid], bv = ((const float4*)b)[tid];
    float4 o4;
    o4.x = (v.x - mean) * rs * gv.x + bv.x;
    o4.y = (v.y - mean) * rs * gv.y + bv.y;
    o4.z = (v.z - mean) * rs * gv.z + bv.z;
    o4.w = (v.w - mean) * rs * gv.w + bv.w;
    ((float4*)(out + (size_t)row * 512))[tid] = o4;
}

// ---------------- layernorm over 128, in place + transposed copy ------------
__global__ void ln128(float* __restrict__ u, float* __restrict__ uT,
                      const float* __restrict__ g, const float* __restrict__ b)
{
    const int warp = threadIdx.x >> 5, lane = threadIdx.x & 31;
    const int row  = blockIdx.x * 8 + warp;
    float4 v = ((const float4*)(u + (size_t)row * 128))[lane];
    float s  = v.x + v.y + v.z + v.w;
    float sq = v.x * v.x + v.y * v.y + v.z * v.z + v.w * v.w;
#pragma unroll
    for (int o = 16; o; o >>= 1) {
        s  += __shfl_xor_sync(0xffffffffu, s, o);
        sq += __shfl_xor_sync(0xffffffffu, sq, o);
    }
    const float mean = s * (1.f / 128.f);
    const float var  = sq * (1.f / 128.f) - mean * mean;
    const float rs   = rsqrtf(var + 1e-5f);
    float4 gv = ((const float4*)g)[lane], bv = ((const float4*)b)[lane];
    float4 o4;
    o4.x = (v.x - mean) * rs * gv.x + bv.x;
    o4.y = (v.y - mean) * rs * gv.y + bv.y;
    o4.z = (v.z - mean) * rs * gv.z + bv.z;
    o4.w = (v.w - mean) * rs * gv.w + bv.w;
    ((float4*)(u + (size_t)row * 128))[lane] = o4;
    const int bb = row >> 13, l = row & 8191;
    float* base = uT + (size_t)bb * 128 * 8192 + l;
    const int h = lane * 4;
    base[(size_t)(h + 0) * 8192] = o4.x;
    base[(size_t)(h + 1) * 8192] = o4.y;
    base[(size_t)(h + 2) * 8192] = o4.z;
    base[(size_t)(h + 3) * 8192] = o4.w;
}

// ---------------- DSS tables -------------------------------------------------
__global__ void dss_tables(const float* __restrict__ lam_re, const float* __restrict__ lam_im,
                           const float* __restrict__ C_re, const float* __restrict__ C_im,
                           float* __restrict__ ArevT_re, float* __restrict__ ArevT_im,
                           float* __restrict__ Ahat_re, float* __restrict__ Ahat_im,
                           float* __restrict__ abar_re, float* __restrict__ abar_im,
                           float* __restrict__ cre, float* __restrict__ cim)
{
    const int n = blockIdx.x * 128 + threadIdx.x;
    if (n >= DST) return;
    const float lre = -expf(lam_re[n]);
    const float lim =  expf(lam_im[n]);
    const float mag = expf(lre);
    const float er = mag * cosf(lim), ei = mag * sinf(lim);
    const float den = lre * lre + lim * lim;
    const float nr = er - 1.f, ni = ei;
    const float wr = (nr * lre + ni * lim) / den;
    const float wi = (ni * lre - nr * lim) / den;
    for (int h = 0; h < DHID; h++) {
        const float a = C_re[h * DST + n], b = C_im[h * DST + n];
        cre[h * DST + n] = a * wr - b * wi;
        cim[h * DST + n] = a * wi + b * wr;
    }
    for (int t = 0; t < TCH; t++) {
        const float x1 = (float)(TCH - 1 - t);
        const float m1 = expf(x1 * lre);
        ArevT_re[n * TCH + t] = m1 * cosf(x1 * lim);
        ArevT_im[n * TCH + t] = m1 * sinf(x1 * lim);
        const float x2 = (float)(t + 1);
        const float m2 = expf(x2 * lre);
        Ahat_re[t * DST + n] = m2 * cosf(x2 * lim);
        Ahat_im[t * DST + n] = m2 * sinf(x2 * lim);
    }
    const float m3 = expf((float)TCH * lre);
    abar_re[n] = m3 * cosf((float)TCH * lim);
    abar_im[n] = m3 * sinf((float)TCH * lim);
}

// kern_chunk[d,h] = Re( sum_n c[h,n] exp(d*lam_n) )
__global__ void kernchunk(const float* __restrict__ lam_re, const float* __restrict__ lam_im,
                          const float* __restrict__ cre, const float* __restrict__ cim,
                          float* __restrict__ kc)
{
    const int d = blockIdx.x, h = threadIdx.x;   // <<<128,128>>>
    __shared__ float er[DST], ei[DST];
    for (int n = h; n < DST; n += 128) {
        const float lre = -expf(lam_re[n]);
        const float lim =  expf(lam_im[n]);
        const float m = expf((float)d * lre);
        er[n] = m * cosf((float)d * lim);
        ei[n] = m * sinf((float)d * lim);
    }
    __syncthreads();
    float s = 0.f;
    for (int n = 0; n < DST; n++)
        s += cre[h * DST + n] * er[n] - cim[h * DST + n] * ei[n];
    kc[d * DHID + h] = s;
}

// ---------------- chunk scan -------------------------------------------------
__global__ void scan_kernel(float* __restrict__ Zre, float* __restrict__ Zim,
                            const float* __restrict__ cre, const float* __restrict__ cim,
                            const float* __restrict__ abr, const float* __restrict__ abi)
{
    const int t = blockIdx.x * 256 + threadIdx.x;   // [0, 262144)
    const int n = t & 511, h = (t >> 9) & 127, b = t >> 16;
    const float ar = abr[n], ai = abi[n];
    const float kr = cre[h * DST + n], ki = cim[h * DST + n];
    float Sr = 0.f, Si = 0.f;
    const size_t stride = (size_t)DHID * DST;
    size_t idx = ((size_t)b * CCH * DHID + h) * DST + n;
    for (int c = 0; c < CCH; c++) {
        const float zr = Zre[idx], zi = Zim[idx];
        Zre[idx] = kr * Sr - ki * Si;
        Zim[idx] = kr * Si + ki * Sr;
        const float t1 = ar * Sr - ai * Si + zr;
        Si = ar * Si + ai * Sr + zi;
        Sr = t1;
        idx += stride;
    }
}

// ---------------- intra-chunk triangular conv + skip residual ---------------
__global__ void intra_kernel(const float* __restrict__ un, const float* __restrict__ kc,
                             float* __restrict__ y, const float* __restrict__ Ds)
{
    extern __shared__ float sm[];
    float* Uc = sm;
    float* Kc = sm + TCH * DHID;
    const size_t base = (size_t)blockIdx.x * TCH * DHID;
    for (int i = threadIdx.x; i < TCH * DHID / 4; i += 256) {
        ((float4*)Uc)[i] = ((const float4*)(un + base))[i];
        ((float4*)Kc)[i] = ((const float4*)kc)[i];
    }
    __syncthreads();
    for (int e = threadIdx.x; e < TCH * DHID; e += 256) {
        const int dt = e >> 7, h = e & 127;
        float s = Uc[dt * DHID + h] * Ds[h];
        for (int j = 0; j <= dt; j++)
            s = fmaf(Kc[(dt - j) * DHID + h], Uc[j * DHID + h], s);
        y[base + e] += s;
    }
}

// ---------------- launch ----------------------------------------------------
extern "C" void kernel_launch(void* const* d_in, const int* in_sizes, int n_in,
                              void* d_out, int out_size)
{
    const float* x      = (const float*)d_in[0];
    const float* norm_g = (const float*)d_in[1];
    const float* norm_b = (const float*)d_in[2];
    const float* W_v    = (const float*)d_in[3];
    const float* W_u    = (const float*)d_in[4];
    const float* W_uc   = (const float*)d_in[5];
    const float* W_o    = (const float*)d_in[6];
    const float* b_o    = (const float*)d_in[7];
    const float* dss_g  = (const float*)d_in[8];
    const float* dss_b  = (const float*)d_in[9];
    const float* lam_re = (const float*)d_in[10];
    const float* lam_im = (const float*)d_in[11];
    const float* C_re   = (const float*)d_in[12];
    const float* C_im   = (const float*)d_in[13];
    const float* D_skip = (const float*)d_in[14];
    float* out = (float*)d_out;

    float *xn, *v, *un, *unT, *y, *Zre, *Zim;
    float *ArT_re, *ArT_im, *Ah_re, *Ah_im, *abr, *abi, *cre, *cim, *kc;
    cudaGetSymbolAddress((void**)&xn,  g_xn);
    cudaGetSymbolAddress((void**)&v,   g_v);
    cudaGetSymbolAddress((void**)&un,  g_un);
    cudaGetSymbolAddress((void**)&unT, g_unT);
    cudaGetSymbolAddress((void**)&y,   g_y);
    cudaGetSymbolAddress((void**)&Zre, g_Zre);
    cudaGetSymbolAddress((void**)&Zim, g_Zim);
    cudaGetSymbolAddress((void**)&ArT_re, g_ArevT_re);
    cudaGetSymbolAddress((void**)&ArT_im, g_ArevT_im);
    cudaGetSymbolAddress((void**)&Ah_re,  g_Ahat_re);
    cudaGetSymbolAddress((void**)&Ah_im,  g_Ahat_im);
    cudaGetSymbolAddress((void**)&abr, g_abar_re);
    cudaGetSymbolAddress((void**)&abi, g_abar_im);
    cudaGetSymbolAddress((void**)&cre, g_cre);
    cudaGetSymbolAddress((void**)&cim, g_cim);
    cudaGetSymbolAddress((void**)&kc,  g_kc);

    // 1) xn = LN(x)
    ln512<<<MROWS, 128>>>(x, norm_g, norm_b, xn);

    // 2) v = gelu(xn @ W_v^T)   [32768 x 2048]
    tgemm<EPI_GELU><<<dim3(DGATE / 128, MROWS / 128, 1), 256>>>(
        DIN, xn, DIN, 0, 0, W_v, DIN, 0, 0, v, DGATE, 0, 0, 1, nullptr, nullptr);

    // 3) u = gelu(xn @ W_u^T)   [32768 x 128]
    tgemm<EPI_GELU><<<dim3(1, MROWS / 128, 1), 256>>>(
        DIN, xn, DIN, 0, 0, W_u, DIN, 0, 0, un, DHID, 0, 0, 1, nullptr, nullptr);

    // 4) un = LN(u); also transposed copy unT[b,h,l]
    ln128<<<MROWS / 8, 256>>>(un, unT, dss_g, dss_b);

    // 5) DSS tables
    dss_tables<<<DST / 128, 128>>>(lam_re, lam_im, C_re, C_im,
                                   ArT_re, ArT_im, Ah_re, Ah_im, abr, abi, cre, cim);
    kernchunk<<<TCH, DHID>>>(lam_re, lam_im, cre, cim, kc);

    // 6) Z[b,c,h,n] = sum_t un[b,cT+t,h] * a_n^{T-1-t}
    tgemm<EPI_STORE><<<dim3(DST / 128, 1, BSZ * CCH), 256>>>(
        TCH,
        unT, LSEQ, (long long)DHID * LSEQ, TCH,
        ArT_re, TCH, 0, 0,
        Zre, DST, (long long)CCH * DHID * DST, (long long)DHID * DST,
        CCH, nullptr, nullptr);
    tgemm<EPI_STORE><<<dim3(DST / 128, 1, BSZ * CCH), 256>>>(
        TCH,
        unT, LSEQ, (long long)DHID * LSEQ, TCH,
        ArT_im, TCH, 0, 0,
        Zim, DST, (long long)CCH * DHID * DST, (long long)DHID * DST,
        CCH, nullptr, nullptr);

    // 7) scan across chunks, P = c * S_start written in place over Z
    scan_kernel<<<(BSZ * DHID * DST) / 256, 256>>>(Zre, Zim, cre, cim, abr, abi);

    // 8) y_inter = Ahat_re @ P_re - Ahat_im @ P_im
    tgemm<EPI_STORE><<<dim3(1, 1, BSZ * CCH), 256>>>(
        DST,
        Ah_re, DST, 0, 0,
        Zre, DST, (long long)CCH * DHID * DST, (long long)DHID * DST,
        y, DHID, (long long)CCH * TCH * DHID, (long long)TCH * DHID,
        CCH, nullptr, nullptr);
    tgemm<EPI_SUB><<<dim3(1, 1, BSZ * CCH), 256>>>(
        DST,
        Ah_im, DST, 0, 0,
        Zim, DST, (long long)CCH * DHID * DST, (long long)DHID * DST,
        y, DHID, (long long)CCH * TCH * DHID, (long long)TCH * DHID,
        CCH, nullptr, nullptr);

    // 9) y += intra-chunk conv + un * D_skip
    cudaFuncSetAttribute(intra_kernel, cudaFuncAttributeMaxDynamicSharedMemorySize,
                         2 * TCH * DHID * (int)sizeof(float));
    intra_kernel<<<BSZ * CCH, 256, 2 * TCH * DHID * sizeof(float)>>>(un, kc, y, D_skip);

    // 10) gv = (y @ W_uc^T) * v   (in place over v)
    tgemm<EPI_MUL><<<dim3(DGATE / 128, MROWS / 128, 1), 256>>>(
        DHID, y, DHID, 0, 0, W_uc, DHID, 0, 0, v, DGATE, 0, 0, 1, nullptr, nullptr);

    // 11) out = gv @ W_o^T + b_o + x
    tgemm<EPI_FINAL><<<dim3(DIN / 128, MROWS / 128, 1), 256>>>(
        DGATE, v, DGATE, 0, 0, W_o, DGATE, 0, 0, out, DIN, 0, 0, 1, b_o, x);
}

// round 5
// speedup vs baseline: 2.3060x; 1.4330x over previous
#include <cuda_runtime.h>
#include <cuda_bf16.h>
#include <cstdint>
#include <math.h>

// Problem dims
#define BSZ   4
#define LSEQ  8192
#define DIN   512
#define DGATE 2048
#define DHID  128
#define DST   512
#define TCH   128
#define CCH   64
#define MROWS (BSZ*LSEQ)   // 32768

typedef __nv_bfloat16 bf16;
typedef __nv_bfloat162 bf162;

// ---------------- scratch (static device globals; no runtime alloc) --------
// fp32 intermediates
__device__ float g_v   [(size_t)MROWS*DGATE];        // gelu gate (fp32 for exact gating)
__device__ float g_un  [(size_t)MROWS*DHID];         // normalized u (intra input)
__device__ float g_y   [(size_t)MROWS*DHID];         // y_inter accumulator
__device__ float g_Zre [(size_t)BSZ*CCH*DHID*DST];
__device__ float g_Zim [(size_t)BSZ*CCH*DHID*DST];
__device__ float g_abar_re [DST];
__device__ float g_abar_im [DST];
__device__ float g_cre     [DHID*DST];
__device__ float g_cim     [DHID*DST];
__device__ float g_kc      [TCH*DHID];
// bf16 split operands
__device__ bf16 g_xnh [(size_t)MROWS*DIN];
__device__ bf16 g_xnl [(size_t)MROWS*DIN];
__device__ bf16 g_unTh[(size_t)BSZ*DHID*LSEQ];
__device__ bf16 g_unTl[(size_t)BSZ*DHID*LSEQ];
__device__ bf16 g_Preh[(size_t)BSZ*CCH*DHID*DST];
__device__ bf16 g_Prel[(size_t)BSZ*CCH*DHID*DST];
__device__ bf16 g_Pimh[(size_t)BSZ*CCH*DHID*DST];
__device__ bf16 g_Piml[(size_t)BSZ*CCH*DHID*DST];
__device__ bf16 g_yh  [(size_t)MROWS*DHID];
__device__ bf16 g_yl  [(size_t)MROWS*DHID];
__device__ bf16 g_gvh [(size_t)MROWS*DGATE];
__device__ bf16 g_gvl [(size_t)MROWS*DGATE];
__device__ bf16 g_Wvh [DGATE*DIN],  g_Wvl [DGATE*DIN];
__device__ bf16 g_Wuh [DHID*DIN],   g_Wul [DHID*DIN];
__device__ bf16 g_Wuch[DGATE*DHID], g_Wucl[DGATE*DHID];
__device__ bf16 g_Woh [DIN*DGATE],  g_Wol [DIN*DGATE];
__device__ bf16 g_ArTRh[DST*TCH], g_ArTRl[DST*TCH];
__device__ bf16 g_ArTIh[DST*TCH], g_ArTIl[DST*TCH];
__device__ bf16 g_AhRh[TCH*DST], g_AhRl[TCH*DST];
__device__ bf16 g_AhIh[TCH*DST], g_AhIl[TCH*DST];

// ---------------- helpers ---------------------------------------------------
__device__ __forceinline__ float gelu_exact(float x) {
    return 0.5f * x * (1.0f + erff(x * 0.70710678118654752440f));
}
__device__ __forceinline__ uint32_t smem_u32(const void* p) {
    uint32_t a;
    asm("{ .reg .u64 t; cvta.to.shared.u64 t, %1; cvt.u32.u64 %0, t; }"
        : "=r"(a) : "l"(p));
    return a;
}
__device__ __forceinline__ void ldm_x4(uint32_t* r, uint32_t addr) {
    asm volatile("ldmatrix.sync.aligned.m8n8.x4.shared.b16 {%0,%1,%2,%3}, [%4];"
        : "=r"(r[0]), "=r"(r[1]), "=r"(r[2]), "=r"(r[3]) : "r"(addr));
}
__device__ __forceinline__ void mma_bf16(float* d, const uint32_t* a, const uint32_t* b) {
    asm volatile(
        "mma.sync.aligned.m16n8k16.row.col.f32.bf16.bf16.f32 "
        "{%0,%1,%2,%3}, {%4,%5,%6,%7}, {%8,%9}, {%0,%1,%2,%3};"
        : "+f"(d[0]), "+f"(d[1]), "+f"(d[2]), "+f"(d[3])
        : "r"(a[0]), "r"(a[1]), "r"(a[2]), "r"(a[3]), "r"(b[0]), "r"(b[1]));
}
__device__ __forceinline__ void cpasync16(uint32_t dst, const void* src) {
    asm volatile("cp.async.cg.shared.global [%0], [%1], 16;" :: "r"(dst), "l"(src));
}
__device__ __forceinline__ void split2(float a, float b, bf162& h, bf162& l) {
    h = __floats2bfloat162_rn(a, b);
    l = __floats2bfloat162_rn(a - __bfloat162float(h.x), b - __bfloat162float(h.y));
}

enum { EPI_STORE = 0, EPI_GELU = 1, EPI_SUB = 3, EPI_FINAL = 4, EPI_MULSPLIT = 5 };

// smem: per stage, 4 buffers (Ahi,Alo,Bhi,Blo) of 128 rows x (64B data + 16B pad)
#define ROWB    80
#define BUFB    (128 * ROWB)     // 10240
#define STAGEB  (4 * BUFB)       // 40960
#define TG_SMEM (2 * STAGEB)     // 81920 (double buffered)

// ---------------- split-bf16 HMMA GEMM, cp.async double-buffered ------------
// C = A(MxK) * B(NxK)^T, operands pre-split to bf16 hi/lo in global.
// 128x128 CTA tile, 8 warps (warp tile 32x64), K chunks of 32.
template <int EPI>
__global__ __launch_bounds__(256)
void tgemm(int K,
           const bf16* __restrict__ Ah, const bf16* __restrict__ Al,
           int lda, long long sAb, long long sAc,
           const bf16* __restrict__ Bh, const bf16* __restrict__ Bl,
           int ldb, long long sBb, long long sBc,
           float* __restrict__ C, int ldc, long long sCb, long long sCc,
           int CB,
           const float* __restrict__ bias, const float* __restrict__ resid,
           bf16* __restrict__ Oh, bf16* __restrict__ Ol)
{
    extern __shared__ __align__(16) char smem[];
    const uint32_t sbase = smem_u32(smem);

    const int tid  = threadIdx.x;
    const int wid  = tid >> 5;
    const int lane = tid & 31;
    const int wm   = wid & 3;     // 4 warps along M
    const int wn   = wid >> 2;    // 2 warps along N

    const int zb = blockIdx.z / CB, zc = blockIdx.z % CB;
    Ah += (size_t)zb * sAb + (size_t)zc * sAc;
    Al += (size_t)zb * sAb + (size_t)zc * sAc;
    Bh += (size_t)zb * sBb + (size_t)zc * sBc;
    Bl += (size_t)zb * sBb + (size_t)zc * sBc;
    C  += (size_t)zb * sCb + (size_t)zc * sCc;
    const int row0 = blockIdx.y * 128;
    const int col0 = blockIdx.x * 128;

    // loader: 8 cp.asyncs/thread per stage; thread -> (buf, row, 16B col)
    const int lrow = (tid >> 2) & 63;     // row within 64-row half
    const int lc16 = tid & 3;
    const uint32_t sdst0 = (uint32_t)(lrow * ROWB + lc16 * 16);

    float acc[2][8][4];
#pragma unroll
    for (int i = 0; i < 2; i++)
#pragma unroll
        for (int j = 0; j < 8; j++)
#pragma unroll
            for (int k = 0; k < 4; k++) acc[i][j][k] = 0.f;

    // ldmatrix smem offsets (within a stage)
    const uint32_t aOff = (uint32_t)((wm * 32 + (lane & 15)) * ROWB + ((lane & 16) ? 16 : 0));
    const uint32_t bOff = (uint32_t)(2 * BUFB +
        (wn * 64 + (lane & 7) + ((lane & 16) ? 8 : 0)) * ROWB + ((lane & 8) ? 16 : 0));

    const int nchunk = K >> 5;

    // ---- issue loads for one stage ----
    auto issue = [&](int st, int k0) {
        const uint32_t sb = sbase + st * STAGEB;
#pragma unroll
        for (int i = 0; i < 8; i++) {
            const int buf  = i >> 1;                  // 0..3
            const int row  = (i & 1) * 64 + lrow;     // 0..127
            const int eoff = k0 + lc16 * 8;
            const bf16* src;
            if      (buf == 0) src = Ah + (size_t)(row0 + row) * lda + eoff;
            else if (buf == 1) src = Al + (size_t)(row0 + row) * lda + eoff;
            else if (buf == 2) src = Bh + (size_t)(col0 + row) * ldb + eoff;
            else               src = Bl + (size_t)(col0 + row) * ldb + eoff;
            cpasync16(sb + buf * BUFB + (i & 1) * (64 * ROWB) + sdst0, src);
        }
    };

    issue(0, 0);
    asm volatile("cp.async.commit_group;" ::: "memory");

    for (int c = 0; c < nchunk; c++) {
        const int cur = c & 1;
        if (c + 1 < nchunk) issue(cur ^ 1, (c + 1) << 5);
        asm volatile("cp.async.commit_group;" ::: "memory");
        asm volatile("cp.async.wait_group 1;" ::: "memory");
        __syncthreads();

        const uint32_t sb = sbase + cur * STAGEB;
#pragma unroll
        for (int k16 = 0; k16 < 2; k16++) {
            uint32_t ahi[2][4], alo[2][4];
#pragma unroll
            for (int mt = 0; mt < 2; mt++) {
                const uint32_t aa = sb + aOff + mt * (16 * ROWB) + k16 * 32;
                ldm_x4(ahi[mt], aa);
                ldm_x4(alo[mt], aa + BUFB);
            }
#pragma unroll
            for (int p = 0; p < 4; p++) {
                const uint32_t ba = sb + bOff + p * (16 * ROWB) + k16 * 32;
                uint32_t bhi[4], blo[4];
                ldm_x4(bhi, ba);
                ldm_x4(blo, ba + BUFB);
#pragma unroll
                for (int mt = 0; mt < 2; mt++) {
#pragma unroll
                    for (int hh = 0; hh < 2; hh++) {
                        float* d = acc[mt][p * 2 + hh];
                        mma_bf16(d, ahi[mt], &bhi[hh * 2]);
                        mma_bf16(d, ahi[mt], &blo[hh * 2]);
                        mma_bf16(d, alo[mt], &bhi[hh * 2]);
                    }
                }
            }
        }
        __syncthreads();
    }

    // ---- epilogue ----
    const int qrow = lane >> 2, qcol = (lane & 3) * 2;
#pragma unroll
    for (int mt = 0; mt < 2; mt++) {
#pragma unroll
        for (int nt = 0; nt < 8; nt++) {
            const int r0r = row0 + wm * 32 + mt * 16 + qrow;
            const int cc  = col0 + wn * 64 + nt * 8 + qcol;
            float* d = acc[mt][nt];
#pragma unroll
            for (int h = 0; h < 2; h++) {
                const int rr = r0r + h * 8;
                const size_t idx = (size_t)rr * ldc + cc;
                float2 o = make_float2(d[h * 2 + 0], d[h * 2 + 1]);
                if (EPI == EPI_GELU) {
                    o.x = gelu_exact(o.x); o.y = gelu_exact(o.y);
                    *(float2*)(C + idx) = o;
                } else if (EPI == EPI_SUB) {
                    const float2 q = *(const float2*)(C + idx);
                    o.x = q.x - o.x; o.y = q.y - o.y;
                    *(float2*)(C + idx) = o;
                } else if (EPI == EPI_FINAL) {
                    const float2 bb = *(const float2*)(bias + cc);
                    const float2 rr2 = *(const float2*)(resid + idx);
                    o.x += bb.x + rr2.x; o.y += bb.y + rr2.y;
                    *(float2*)(C + idx) = o;
                } else if (EPI == EPI_MULSPLIT) {
                    const float2 q = *(const float2*)(C + idx);   // gate v (fp32)
                    o.x *= q.x; o.y *= q.y;
                    bf162 hh2, ll2; split2(o.x, o.y, hh2, ll2);
                    *(bf162*)(Oh + idx) = hh2;
                    *(bf162*)(Ol + idx) = ll2;
                } else {  // EPI_STORE
                    *(float2*)(C + idx) = o;
                }
            }
        }
    }
}

// ---------------- layernorm over 512 -> split bf16 --------------------------
__global__ void ln512(const float* __restrict__ x, const float* __restrict__ g,
                      const float* __restrict__ b,
                      bf16* __restrict__ xnh, bf16* __restrict__ xnl)
{
    const int row = blockIdx.x, tid = threadIdx.x;  // 128 threads
    float4 v = ((const float4*)(x + (size_t)row * 512))[tid];
    float s  = v.x + v.y + v.z + v.w;
    float sq = v.x * v.x + v.y * v.y + v.z * v.z + v.w * v.w;
#pragma unroll
    for (int o = 16; o; o >>= 1) {
        s  += __shfl_xor_sync(0xffffffffu, s, o);
        sq += __shfl_xor_sync(0xffffffffu, sq, o);
    }
    __shared__ float ss[4], ssq[4];
    if ((tid & 31) == 0) { ss[tid >> 5] = s; ssq[tid >> 5] = sq; }
    __syncthreads();
    s  = ss[0] + ss[1] + ss[2] + ss[3];
    sq = ssq[0] + ssq[1] + ssq[2] + ssq[3];
    const float mean = s * (1.f / 512.f);
    const float var  = sq * (1.f / 512.f) - mean * mean;
    const float rs   = rsqrtf(var + 1e-5f);
    float4 gv = ((const float4*)g)[tid], bv = ((const float4*)b)[tid];
    float4 o4;
    o4.x = (v.x - mean) * rs * gv.x + bv.x;
    o4.y = (v.y - mean) * rs * gv.y + bv.y;
    o4.z = (v.z - mean) * rs * gv.z + bv.z;
    o4.w = (v.w - mean) * rs * gv.w + bv.w;
    bf162 h01, l01, h23, l23;
    split2(o4.x, o4.y, h01, l01);
    split2(o4.z, o4.w, h23, l23);
    uint2 hv, lv;
    hv.x = *(uint32_t*)&h01; hv.y = *(uint32_t*)&h23;
    lv.x = *(uint32_t*)&l01; lv.y = *(uint32_t*)&l23;
    *(uint2*)(xnh + (size_t)row * 512 + tid * 4) = hv;
    *(uint2*)(xnl + (size_t)row * 512 + tid * 4) = lv;
}

// ---------------- layernorm over 128: un fp32 in place + unT split ----------
__global__ void ln128(float* __restrict__ u, bf16* __restrict__ uTh,
                      bf16* __restrict__ uTl,
                      const float* __restrict__ g, const float* __restrict__ b)
{
    const int warp = threadIdx.x >> 5, lane = threadIdx.x & 31;
    const int row  = blockIdx.x * 8 + warp;
    float4 v = ((const float4*)(u + (size_t)row * 128))[lane];
    float s  = v.x + v.y + v.z + v.w;
    float sq = v.x * v.x + v.y * v.y + v.z * v.z + v.w * v.w;
#pragma unroll
    for (int o = 16; o; o >>= 1) {
        s  += __shfl_xor_sync(0xffffffffu, s, o);
        sq += __shfl_xor_sync(0xffffffffu, sq, o);
    }
    const float mean = s * (1.f / 128.f);
    const float var  = sq * (1.f / 128.f) - mean * mean;
    const float rs   = rsqrtf(var + 1e-5f);
    float4 gv = ((const float4*)g)[lane], bv = ((const float4*)b)[lane];
    float4 o4;
    o4.x = (v.x - mean) * rs * gv.x + bv.x;
    o4.y = (v.y - mean) * rs * gv.y + bv.y;
    o4.z = (v.z - mean) * rs * gv.z + bv.z;
    o4.w = (v.w - mean) * rs * gv.w + bv.w;
    ((float4*)(u + (size_t)row * 128))[lane] = o4;
    const int bb = row >> 13, l = row & 8191;
    const size_t tbase = (size_t)bb * 128 * 8192 + l;
    const int h = lane * 4;
    float vals[4] = {o4.x, o4.y, o4.z, o4.w};
#pragma unroll
    for (int k = 0; k < 4; k++) {
        bf16 hh = __float2bfloat16(vals[k]);
        uTh[tbase + (size_t)(h + k) * 8192] = hh;
        uTl[tbase + (size_t)(h + k) * 8192] = __float2bfloat16(vals[k] - __bfloat162float(hh));
    }
}

// ---------------- DSS tables (split table outputs) ---------------------------
__global__ void dss_tables(const float* __restrict__ lam_re, const float* __restrict__ lam_im,
                           const float* __restrict__ C_re, const float* __restrict__ C_im,
                           bf16* ArTRh, bf16* ArTRl, bf16* ArTIh, bf16* ArTIl,
                           bf16* AhRh, bf16* AhRl, bf16* AhIh, bf16* AhIl,
                           float* __restrict__ abar_re, float* __restrict__ abar_im,
                           float* __restrict__ cre, float* __restrict__ cim)
{
    const int n = blockIdx.x * 128 + threadIdx.x;
    if (n >= DST) return;
    const float lre = -expf(lam_re[n]);
    const float lim =  expf(lam_im[n]);
    const float mag = expf(lre);
    const float er = mag * cosf(lim), ei = mag * sinf(lim);
    const float den = lre * lre + lim * lim;
    const float nr = er - 1.f, ni = ei;
    const float wr = (nr * lre + ni * lim) / den;
    const float wi = (ni * lre - nr * lim) / den;
    for (int h = 0; h < DHID; h++) {
        const float a = C_re[h * DST + n], b = C_im[h * DST + n];
        cre[h * DST + n] = a * wr - b * wi;
        cim[h * DST + n] = a * wi + b * wr;
    }
    for (int t = 0; t < TCH; t++) {
        const float x1 = (float)(TCH - 1 - t);
        const float m1 = expf(x1 * lre);
        const float vr = m1 * cosf(x1 * lim), vi = m1 * sinf(x1 * lim);
        bf16 hr = __float2bfloat16(vr);
        ArTRh[n * TCH + t] = hr;
        ArTRl[n * TCH + t] = __float2bfloat16(vr - __bfloat162float(hr));
        bf16 hi = __float2bfloat16(vi);
        ArTIh[n * TCH + t] = hi;
        ArTIl[n * TCH + t] = __float2bfloat16(vi - __bfloat162float(hi));
        const float x2 = (float)(t + 1);
        const float m2 = expf(x2 * lre);
        const float wr2 = m2 * cosf(x2 * lim), wi2 = m2 * sinf(x2 * lim);
        bf16 h2 = __float2bfloat16(wr2);
        AhRh[t * DST + n] = h2;
        AhRl[t * DST + n] = __float2bfloat16(wr2 - __bfloat162float(h2));
        bf16 h3 = __float2bfloat16(wi2);
        AhIh[t * DST + n] = h3;
        AhIl[t * DST + n] = __float2bfloat16(wi2 - __bfloat162float(h3));
    }
    const float m3 = expf((float)TCH * lre);
    abar_re[n] = m3 * cosf((float)TCH * lim);
    abar_im[n] = m3 * sinf((float)TCH * lim);
}

// kern_chunk[d,h] = Re( sum_n c[h,n] exp(d*lam_n) )
__global__ void kernchunk(const float* __restrict__ lam_re, const float* __restrict__ lam_im,
                          const float* __restrict__ cre, const float* __restrict__ cim,
                          float* __restrict__ kc)
{
    const int d = blockIdx.x, h = threadIdx.x;   // <<<128,128>>>
    __shared__ float er[DST], ei[DST];
    for (int n = h; n < DST; n += 128) {
        const float lre = -expf(lam_re[n]);
        const float lim =  expf(lam_im[n]);
        const float m = expf((float)d * lre);
        er[n] = m * cosf((float)d * lim);
        ei[n] = m * sinf((float)d * lim);
    }
    __syncthreads();
    float s = 0.f;
    for (int n = 0; n < DST; n++)
        s += cre[h * DST + n] * er[n] - cim[h * DST + n] * ei[n];
    kc[d * DHID + h] = s;
}

// ---------------- chunk scan: fp32 Z in, split bf16 P out --------------------
__global__ void scan_kernel(const float* __restrict__ Zre, const float* __restrict__ Zim,
                            bf16* __restrict__ Preh, bf16* __restrict__ Prel,
                            bf16* __restrict__ Pimh, bf16* __restrict__ Piml,
                            const float* __restrict__ cre, const float* __restrict__ cim,
                            const float* __restrict__ abr, const float* __restrict__ abi)
{
    const int t = blockIdx.x * 256 + threadIdx.x;   // [0, 262144)
    const int n = t & 511, h = (t >> 9) & 127, b = t >> 16;
    const float ar = abr[n], ai = abi[n];
    const float kr = cre[h * DST + n], ki = cim[h * DST + n];
    float Sr = 0.f, Si = 0.f;
    const size_t stride = (size_t)DHID * DST;
    size_t idx = ((size_t)b * CCH * DHID + h) * DST + n;
    for (int c = 0; c < CCH; c++) {
        const float zr = Zre[idx], zi = Zim[idx];
        const float pr = kr * Sr - ki * Si;
        const float pi = kr * Si + ki * Sr;
        bf16 ph = __float2bfloat16(pr);
        Preh[idx] = ph; Prel[idx] = __float2bfloat16(pr - __bfloat162float(ph));
        bf16 qh = __float2bfloat16(pi);
        Pimh[idx] = qh; Piml[idx] = __float2bfloat16(pi - __bfloat162float(qh));
        const float t1 = ar * Sr - ai * Si + zr;
        Si = ar * Si + ai * Sr + zi;
        Sr = t1;
        idx += stride;
    }
}

// ---------------- intra-chunk conv + skip; writes split y --------------------
__global__ void intra_kernel(const float* __restrict__ un, const float* __restrict__ kc,
                             const float* __restrict__ y, const float* __restrict__ Ds,
                             bf16* __restrict__ yh, bf16* __restrict__ yl)
{
    extern __shared__ float sm[];
    float* Uc = sm;
    float* Kc = sm + TCH * DHID;
    const size_t base = (size_t)blockIdx.x * TCH * DHID;
    for (int i = threadIdx.x; i < TCH * DHID / 4; i += 256) {
        ((float4*)Uc)[i] = ((const float4*)(un + base))[i];
        ((float4*)Kc)[i] = ((const float4*)kc)[i];
    }
    __syncthreads();
    for (int e = threadIdx.x; e < TCH * DHID; e += 256) {
        const int dt = e >> 7, h = e & 127;
        float s = Uc[dt * DHID + h] * Ds[h] + y[base + e];
        for (int j = 0; j <= dt; j++)
            s = fmaf(Kc[(dt - j) * DHID + h], Uc[j * DHID + h], s);
        bf16 hh = __float2bfloat16(s);
        yh[base + e] = hh;
        yl[base + e] = __float2bfloat16(s - __bfloat162float(hh));
    }
}

// ---------------- generic fp32 -> bf16 hi/lo split ---------------------------
__global__ void fsplit(const float* __restrict__ s, bf16* __restrict__ h,
                       bf16* __restrict__ l, int n)
{
    const int i = blockIdx.x * 256 + threadIdx.x;
    if (i >= n) return;
    const float v = s[i];
    bf16 hh = __float2bfloat16(v);
    h[i] = hh;
    l[i] = __float2bfloat16(v - __bfloat162float(hh));
}

// ---------------- launch ----------------------------------------------------
extern "C" void kernel_launch(void* const* d_in, const int* in_sizes, int n_in,
                              void* d_out, int out_size)
{
    const float* x      = (const float*)d_in[0];
    const float* norm_g = (const float*)d_in[1];
    const float* norm_b = (const float*)d_in[2];
    const float* W_v    = (const float*)d_in[3];
    const float* W_u    = (const float*)d_in[4];
    const float* W_uc   = (const float*)d_in[5];
    const float* W_o    = (const float*)d_in[6];
    const float* b_o    = (const float*)d_in[7];
    const float* dss_g  = (const float*)d_in[8];
    const float* dss_b  = (const float*)d_in[9];
    const float* lam_re = (const float*)d_in[10];
    const float* lam_im = (const float*)d_in[11];
    const float* C_re   = (const float*)d_in[12];
    const float* C_im   = (const float*)d_in[13];
    const float* D_skip = (const float*)d_in[14];
    float* out = (float*)d_out;

    float *v, *un, *y, *Zre, *Zim, *abr, *abi, *cre, *cim, *kc;
    bf16 *xnh, *xnl, *unTh, *unTl, *Preh, *Prel, *Pimh, *Piml, *yh, *yl, *gvh, *gvl;
    bf16 *Wvh, *Wvl, *Wuh, *Wul, *Wuch, *Wucl, *Woh, *Wol;
    bf16 *ArTRh, *ArTRl, *ArTIh, *ArTIl, *AhRh, *AhRl, *AhIh, *AhIl;
    cudaGetSymbolAddress((void**)&v,   g_v);
    cudaGetSymbolAddress((void**)&un,  g_un);
    cudaGetSymbolAddress((void**)&y,   g_y);
    cudaGetSymbolAddress((void**)&Zre, g_Zre);
    cudaGetSymbolAddress((void**)&Zim, g_Zim);
    cudaGetSymbolAddress((void**)&abr, g_abar_re);
    cudaGetSymbolAddress((void**)&abi, g_abar_im);
    cudaGetSymbolAddress((void**)&cre, g_cre);
    cudaGetSymbolAddress((void**)&cim, g_cim);
    cudaGetSymbolAddress((void**)&kc,  g_kc);
    cudaGetSymbolAddress((void**)&xnh, g_xnh);
    cudaGetSymbolAddress((void**)&xnl, g_xnl);
    cudaGetSymbolAddress((void**)&unTh, g_unTh);
    cudaGetSymbolAddress((void**)&unTl, g_unTl);
    cudaGetSymbolAddress((void**)&Preh, g_Preh);
    cudaGetSymbolAddress((void**)&Prel, g_Prel);
    cudaGetSymbolAddress((void**)&Pimh, g_Pimh);
    cudaGetSymbolAddress((void**)&Piml, g_Piml);
    cudaGetSymbolAddress((void**)&yh,  g_yh);
    cudaGetSymbolAddress((void**)&yl,  g_yl);
    cudaGetSymbolAddress((void**)&gvh, g_gvh);
    cudaGetSymbolAddress((void**)&gvl, g_gvl);
    cudaGetSymbolAddress((void**)&Wvh, g_Wvh);
    cudaGetSymbolAddress((void**)&Wvl, g_Wvl);
    cudaGetSymbolAddress((void**)&Wuh, g_Wuh);
    cudaGetSymbolAddress((void**)&Wul, g_Wul);
    cudaGetSymbolAddress((void**)&Wuch, g_Wuch);
    cudaGetSymbolAddress((void**)&Wucl, g_Wucl);
    cudaGetSymbolAddress((void**)&Woh, g_Woh);
    cudaGetSymbolAddress((void**)&Wol, g_Wol);
    cudaGetSymbolAddress((void**)&ArTRh, g_ArTRh);
    cudaGetSymbolAddress((void**)&ArTRl, g_ArTRl);
    cudaGetSymbolAddress((void**)&ArTIh, g_ArTIh);
    cudaGetSymbolAddress((void**)&ArTIl, g_ArTIl);
    cudaGetSymbolAddress((void**)&AhRh, g_AhRh);
    cudaGetSymbolAddress((void**)&AhRl, g_AhRl);
    cudaGetSymbolAddress((void**)&AhIh, g_AhIh);
    cudaGetSymbolAddress((void**)&AhIl, g_AhIl);

    cudaFuncSetAttribute(tgemm<EPI_STORE>, cudaFuncAttributeMaxDynamicSharedMemorySize, TG_SMEM);
    cudaFuncSetAttribute(tgemm<EPI_GELU>,  cudaFuncAttributeMaxDynamicSharedMemorySize, TG_SMEM);
    cudaFuncSetAttribute(tgemm<EPI_SUB>,   cudaFuncAttributeMaxDynamicSharedMemorySize, TG_SMEM);
    cudaFuncSetAttribute(tgemm<EPI_FINAL>, cudaFuncAttributeMaxDynamicSharedMemorySize, TG_SMEM);
    cudaFuncSetAttribute(tgemm<EPI_MULSPLIT>, cudaFuncAttributeMaxDynamicSharedMemorySize, TG_SMEM);

    // 0) split weights (bf16 hi/lo)
    fsplit<<<(DGATE * DIN + 255) / 256, 256>>>(W_v, Wvh, Wvl, DGATE * DIN);
    fsplit<<<(DHID * DIN + 255) / 256, 256>>>(W_u, Wuh, Wul, DHID * DIN);
    fsplit<<<(DGATE * DHID + 255) / 256, 256>>>(W_uc, Wuch, Wucl, DGATE * DHID);
    fsplit<<<(DIN * DGATE + 255) / 256, 256>>>(W_o, Woh, Wol, DIN * DGATE);

    // 1) xn = LN(x) -> split
    ln512<<<MROWS, 128>>>(x, norm_g, norm_b, xnh, xnl);

    // 2) v = gelu(xn @ W_v^T)   [32768 x 2048] fp32
    tgemm<EPI_GELU><<<dim3(DGATE / 128, MROWS / 128, 1), 256, TG_SMEM>>>(
        DIN, xnh, xnl, DIN, 0, 0, Wvh, Wvl, DIN, 0, 0,
        v, DGATE, 0, 0, 1, nullptr, nullptr, nullptr, nullptr);

    // 3) u = gelu(xn @ W_u^T)   [32768 x 128] fp32
    tgemm<EPI_GELU><<<dim3(1, MROWS / 128, 1), 256, TG_SMEM>>>(
        DIN, xnh, xnl, DIN, 0, 0, Wuh, Wul, DIN, 0, 0,
        un, DHID, 0, 0, 1, nullptr, nullptr, nullptr, nullptr);

    // 4) un = LN(u) fp32 in place; unT split
    ln128<<<MROWS / 8, 256>>>(un, unTh, unTl, dss_g, dss_b);

    // 5) DSS tables
    dss_tables<<<DST / 128, 128>>>(lam_re, lam_im, C_re, C_im,
                                   ArTRh, ArTRl, ArTIh, ArTIl,
                                   AhRh, AhRl, AhIh, AhIl, abr, abi, cre, cim);
    kernchunk<<<TCH, DHID>>>(lam_re, lam_im, cre, cim, kc);

    // 6) Z[b,c,h,n] = sum_t unT[b,h,cT+t] * ArevT[n,t]   fp32 out
    tgemm<EPI_STORE><<<dim3(DST / 128, 1, BSZ * CCH), 256, TG_SMEM>>>(
        TCH, unTh, unTl, LSEQ, (long long)DHID * LSEQ, TCH,
        ArTRh, ArTRl, TCH, 0, 0,
        Zre, DST, (long long)CCH * DHID * DST, (long long)DHID * DST,
        CCH, nullptr, nullptr, nullptr, nullptr);
    tgemm<EPI_STORE><<<dim3(DST / 128, 1, BSZ * CCH), 256, TG_SMEM>>>(
        TCH, unTh, unTl, LSEQ, (long long)DHID * LSEQ, TCH,
        ArTIh, ArTIl, TCH, 0, 0,
        Zim, DST, (long long)CCH * DHID * DST, (long long)DHID * DST,
        CCH, nullptr, nullptr, nullptr, nullptr);

    // 7) scan across chunks, P = c * S_start split bf16
    scan_kernel<<<(BSZ * DHID * DST) / 256, 256>>>(Zre, Zim, Preh, Prel, Pimh, Piml,
                                                   cre, cim, abr, abi);

    // 8) y_inter = AhatR @ PreT - AhatI @ PimT   fp32
    tgemm<EPI_STORE><<<dim3(1, 1, BSZ * CCH), 256, TG_SMEM>>>(
        DST, AhRh, AhRl, DST, 0, 0,
        Preh, Prel, DST, (long long)CCH * DHID * DST, (long long)DHID * DST,
        y, DHID, (long long)CCH * TCH * DHID, (long long)TCH * DHID,
        CCH, nullptr, nullptr, nullptr, nullptr);
    tgemm<EPI_SUB><<<dim3(1, 1, BSZ * CCH), 256, TG_SMEM>>>(
        DST, AhIh, AhIl, DST, 0, 0,
        Pimh, Piml, DST, (long long)CCH * DHID * DST, (long long)DHID * DST,
        y, DHID, (long long)CCH * TCH * DHID, (long long)TCH * DHID,
        CCH, nullptr, nullptr, nullptr, nullptr);

    // 9) y += intra conv + skip; write split y
    cudaFuncSetAttribute(intra_kernel, cudaFuncAttributeMaxDynamicSharedMemorySize,
                         2 * TCH * DHID * (int)sizeof(float));
    intra_kernel<<<BSZ * CCH, 256, 2 * TCH * DHID * sizeof(float)>>>(un, kc, y, D_skip, yh, yl);

    // 10) gv = (y @ W_uc^T) * v  -> split bf16
    tgemm<EPI_MULSPLIT><<<dim3(DGATE / 128, MROWS / 128, 1), 256, TG_SMEM>>>(
        DHID, yh, yl, DHID, 0, 0, Wuch, Wucl, DHID, 0, 0,
        v, DGATE, 0, 0, 1, nullptr, nullptr, gvh, gvl);

    // 11) out = gv @ W_o^T + b_o + x
    tgemm<EPI_FINAL><<<dim3(DIN / 128, MROWS / 128, 1), 256, TG_SMEM>>>(
        DGATE, gvh, gvl, DGATE, 0, 0, Woh, Wol, DGATE, 0, 0,
        out, DIN, 0, 0, 1, b_o, x, nullptr, nullptr);
}

// round 6
// speedup vs baseline: 2.7709x; 1.2016x over previous
#include <cuda_runtime.h>
#include <cuda_bf16.h>
#include <cstdint>
#include <math.h>

// Problem dims
#define BSZ   4
#define LSEQ  8192
#define DIN   512
#define DGATE 2048
#define DHID  128
#define DST   512
#define TCH   128
#define CCH   64
#define MROWS (BSZ*LSEQ)   // 32768

typedef __nv_bfloat16 bf16;
typedef __nv_bfloat162 bf162;

// ---------------- scratch (static device globals; no runtime alloc) --------
__device__ float g_v   [(size_t)MROWS*DGATE];
__device__ float g_un  [(size_t)MROWS*DHID];
__device__ float g_y   [(size_t)MROWS*DHID];
__device__ float g_Zre [(size_t)BSZ*CCH*DHID*DST];
__device__ float g_Zim [(size_t)BSZ*CCH*DHID*DST];
__device__ float g_abar_re [DST];
__device__ float g_abar_im [DST];
__device__ float g_cre     [DHID*DST];
__device__ float g_cim     [DHID*DST];
__device__ float g_kc      [TCH*DHID];
// bf16 split operands
__device__ bf16 g_xnh [(size_t)MROWS*DIN];
__device__ bf16 g_xnl [(size_t)MROWS*DIN];
__device__ bf16 g_unTh[(size_t)BSZ*DHID*LSEQ];
__device__ bf16 g_unTl[(size_t)BSZ*DHID*LSEQ];
// concatenated P = [Pre | Pim] along k (1024)
__device__ bf16 g_Pch [(size_t)BSZ*CCH*DHID*1024];
__device__ bf16 g_Pcl [(size_t)BSZ*CCH*DHID*1024];
__device__ bf16 g_yh  [(size_t)MROWS*DHID];
__device__ bf16 g_yl  [(size_t)MROWS*DHID];
__device__ bf16 g_gvh [(size_t)MROWS*DGATE];
__device__ bf16 g_gvl [(size_t)MROWS*DGATE];
__device__ bf16 g_Wvh [DGATE*DIN],  g_Wvl [DGATE*DIN];
__device__ bf16 g_Wuh [DHID*DIN],   g_Wul [DHID*DIN];
__device__ bf16 g_Wuch[DGATE*DHID], g_Wucl[DGATE*DHID];
__device__ bf16 g_Woh [DIN*DGATE],  g_Wol [DIN*DGATE];
__device__ bf16 g_ArTRh[DST*TCH], g_ArTRl[DST*TCH];
__device__ bf16 g_ArTIh[DST*TCH], g_ArTIl[DST*TCH];
// concatenated Ahat' = [AhR | -AhI] along k (1024)
__device__ bf16 g_AhCh[TCH*1024], g_AhCl[TCH*1024];

// ---------------- helpers ---------------------------------------------------
__device__ __forceinline__ float gelu_exact(float x) {
    return 0.5f * x * (1.0f + erff(x * 0.70710678118654752440f));
}
__device__ __forceinline__ uint32_t smem_u32(const void* p) {
    uint32_t a;
    asm("{ .reg .u64 t; cvta.to.shared.u64 t, %1; cvt.u32.u64 %0, t; }"
        : "=r"(a) : "l"(p));
    return a;
}
__device__ __forceinline__ void ldm_x4(uint32_t* r, uint32_t addr) {
    asm volatile("ldmatrix.sync.aligned.m8n8.x4.shared.b16 {%0,%1,%2,%3}, [%4];"
        : "=r"(r[0]), "=r"(r[1]), "=r"(r[2]), "=r"(r[3]) : "r"(addr));
}
__device__ __forceinline__ void mma_bf16(float* d, const uint32_t* a, const uint32_t* b) {
    asm volatile(
        "mma.sync.aligned.m16n8k16.row.col.f32.bf16.bf16.f32 "
        "{%0,%1,%2,%3}, {%4,%5,%6,%7}, {%8,%9}, {%0,%1,%2,%3};"
        : "+f"(d[0]), "+f"(d[1]), "+f"(d[2]), "+f"(d[3])
        : "r"(a[0]), "r"(a[1]), "r"(a[2]), "r"(a[3]), "r"(b[0]), "r"(b[1]));
}
__device__ __forceinline__ void cpasync16(uint32_t dst, const void* src) {
    asm volatile("cp.async.cg.shared.global [%0], [%1], 16;" :: "r"(dst), "l"(src));
}
__device__ __forceinline__ void split2(float a, float b, bf162& h, bf162& l) {
    h = __floats2bfloat162_rn(a, b);
    l = __floats2bfloat162_rn(a - __bfloat162float(h.x), b - __bfloat162float(h.y));
}

enum { EPI_STORE = 0, EPI_GELU = 1, EPI_FINAL = 4, EPI_MULSPLIT = 5 };

// smem: per stage, 4 buffers (Ahi,Alo,Bhi,Blo) of 128 rows x (64B data + 16B pad)
#define ROWB    80
#define BUFB    (128 * ROWB)     // 10240
#define STAGEB  (4 * BUFB)       // 40960
#define TG_SMEM (2 * STAGEB)     // 81920 (double buffered)

// ---------------- split-bf16 HMMA GEMM, cp.async double-buffered ------------
// C = A(MxK) * B(NxK)^T, operands pre-split to bf16 hi/lo in global.
// 128x128 CTA tile, 8 warps (warp tile 32x64), K chunks of 32.
// Single __syncthreads per chunk; issue(c+1) after barrier (hazard-free).
template <int EPI>
__global__ __launch_bounds__(256, 2)
void tgemm(int K,
           const bf16* __restrict__ Ah, const bf16* __restrict__ Al,
           int lda, long long sAb, long long sAc,
           const bf16* __restrict__ Bh, const bf16* __restrict__ Bl,
           int ldb, long long sBb, long long sBc,
           float* __restrict__ C, int ldc, long long sCb, long long sCc,
           int CB,
           const float* __restrict__ bias, const float* __restrict__ resid,
           bf16* __restrict__ Oh, bf16* __restrict__ Ol)
{
    extern __shared__ __align__(16) char smem[];
    const uint32_t sbase = smem_u32(smem);

    const int tid  = threadIdx.x;
    const int wid  = tid >> 5;
    const int lane = tid & 31;
    const int wm   = wid & 3;     // 4 warps along M
    const int wn   = wid >> 2;    // 2 warps along N

    const int zb = blockIdx.z / CB, zc = blockIdx.z % CB;
    Ah += (size_t)zb * sAb + (size_t)zc * sAc;
    Al += (size_t)zb * sAb + (size_t)zc * sAc;
    Bh += (size_t)zb * sBb + (size_t)zc * sBc;
    Bl += (size_t)zb * sBb + (size_t)zc * sBc;
    C  += (size_t)zb * sCb + (size_t)zc * sCc;
    const int row0 = blockIdx.y * 128;
    const int col0 = blockIdx.x * 128;

    // loader: 8 cp.asyncs/thread per stage
    const int lrow = (tid >> 2) & 63;
    const int lc16 = tid & 3;
    const uint32_t sdst0 = (uint32_t)(lrow * ROWB + lc16 * 16);

    float acc[2][8][4];
#pragma unroll
    for (int i = 0; i < 2; i++)
#pragma unroll
        for (int j = 0; j < 8; j++)
#pragma unroll
            for (int k = 0; k < 4; k++) acc[i][j][k] = 0.f;

    const uint32_t aOff = (uint32_t)((wm * 32 + (lane & 15)) * ROWB + ((lane & 16) ? 16 : 0));
    const uint32_t bOff = (uint32_t)(2 * BUFB +
        (wn * 64 + (lane & 7) + ((lane & 16) ? 8 : 0)) * ROWB + ((lane & 8) ? 16 : 0));

    const int nchunk = K >> 5;

    auto issue = [&](int st, int k0) {
        const uint32_t sb = sbase + st * STAGEB;
#pragma unroll
        for (int i = 0; i < 8; i++) {
            const int buf  = i >> 1;
            const int row  = (i & 1) * 64 + lrow;
            const int eoff = k0 + lc16 * 8;
            const bf16* src;
            if      (buf == 0) src = Ah + (size_t)(row0 + row) * lda + eoff;
            else if (buf == 1) src = Al + (size_t)(row0 + row) * lda + eoff;
            else if (buf == 2) src = Bh + (size_t)(col0 + row) * ldb + eoff;
            else               src = Bl + (size_t)(col0 + row) * ldb + eoff;
            cpasync16(sb + buf * BUFB + (i & 1) * (64 * ROWB) + sdst0, src);
        }
        asm volatile("cp.async.commit_group;" ::: "memory");
    };

    issue(0, 0);

    for (int c = 0; c < nchunk; c++) {
        asm volatile("cp.async.wait_group 0;" ::: "memory");
        __syncthreads();
        // safe to issue into the other stage: every warp has finished reading it
        if (c + 1 < nchunk) issue((c + 1) & 1, (c + 1) << 5);

        const uint32_t sb = sbase + (c & 1) * STAGEB;
#pragma unroll
        for (int k16 = 0; k16 < 2; k16++) {
            uint32_t ahi[2][4], alo[2][4];
#pragma unroll
            for (int mt = 0; mt < 2; mt++) {
                const uint32_t aa = sb + aOff + mt * (16 * ROWB) + k16 * 32;
                ldm_x4(ahi[mt], aa);
                ldm_x4(alo[mt], aa + BUFB);
            }
#pragma unroll
            for (int p = 0; p < 4; p++) {
                const uint32_t ba = sb + bOff + p * (16 * ROWB) + k16 * 32;
                uint32_t bhi[4], blo[4];
                ldm_x4(bhi, ba);
                ldm_x4(blo, ba + BUFB);
#pragma unroll
                for (int mt = 0; mt < 2; mt++) {
#pragma unroll
                    for (int hh = 0; hh < 2; hh++) {
                        float* d = acc[mt][p * 2 + hh];
                        mma_bf16(d, ahi[mt], &bhi[hh * 2]);
                        mma_bf16(d, ahi[mt], &blo[hh * 2]);
                        mma_bf16(d, alo[mt], &bhi[hh * 2]);
                    }
                }
            }
        }
    }

    // ---- epilogue ----
    const int qrow = lane >> 2, qcol = (lane & 3) * 2;
#pragma unroll
    for (int mt = 0; mt < 2; mt++) {
#pragma unroll
        for (int nt = 0; nt < 8; nt++) {
            const int r0r = row0 + wm * 32 + mt * 16 + qrow;
            const int cc  = col0 + wn * 64 + nt * 8 + qcol;
            float* d = acc[mt][nt];
#pragma unroll
            for (int h = 0; h < 2; h++) {
                const int rr = r0r + h * 8;
                const size_t idx = (size_t)rr * ldc + cc;
                float2 o = make_float2(d[h * 2 + 0], d[h * 2 + 1]);
                if (EPI == EPI_GELU) {
                    o.x = gelu_exact(o.x); o.y = gelu_exact(o.y);
                    *(float2*)(C + idx) = o;
                } else if (EPI == EPI_FINAL) {
                    const float2 bb = *(const float2*)(bias + cc);
                    const float2 rr2 = *(const float2*)(resid + idx);
                    o.x += bb.x + rr2.x; o.y += bb.y + rr2.y;
                    *(float2*)(C + idx) = o;
                } else if (EPI == EPI_MULSPLIT) {
                    const float2 q = *(const float2*)(C + idx);   // gate v (fp32)
                    o.x *= q.x; o.y *= q.y;
                    bf162 hh2, ll2; split2(o.x, o.y, hh2, ll2);
                    *(bf162*)(Oh + idx) = hh2;
                    *(bf162*)(Ol + idx) = ll2;
                } else {  // EPI_STORE
                    *(float2*)(C + idx) = o;
                }
            }
        }
    }
}

// ---------------- layernorm over 512 -> split bf16 --------------------------
__global__ void ln512(const float* __restrict__ x, const float* __restrict__ g,
                      const float* __restrict__ b,
                      bf16* __restrict__ xnh, bf16* __restrict__ xnl)
{
    const int row = blockIdx.x, tid = threadIdx.x;  // 128 threads
    float4 v = ((const float4*)(x + (size_t)row * 512))[tid];
    float s  = v.x + v.y + v.z + v.w;
    float sq = v.x * v.x + v.y * v.y + v.z * v.z + v.w * v.w;
#pragma unroll
    for (int o = 16; o; o >>= 1) {
        s  += __shfl_xor_sync(0xffffffffu, s, o);
        sq += __shfl_xor_sync(0xffffffffu, sq, o);
    }
    __shared__ float ss[4], ssq[4];
    if ((tid & 31) == 0) { ss[tid >> 5] = s; ssq[tid >> 5] = sq; }
    __syncthreads();
    s  = ss[0] + ss[1] + ss[2] + ss[3];
    sq = ssq[0] + ssq[1] + ssq[2] + ssq[3];
    const float mean = s * (1.f / 512.f);
    const float var  = sq * (1.f / 512.f) - mean * mean;
    const float rs   = rsqrtf(var + 1e-5f);
    float4 gv = ((const float4*)g)[tid], bv = ((const float4*)b)[tid];
    float4 o4;
    o4.x = (v.x - mean) * rs * gv.x + bv.x;
    o4.y = (v.y - mean) * rs * gv.y + bv.y;
    o4.z = (v.z - mean) * rs * gv.z + bv.z;
    o4.w = (v.w - mean) * rs * gv.w + bv.w;
    bf162 h01, l01, h23, l23;
    split2(o4.x, o4.y, h01, l01);
    split2(o4.z, o4.w, h23, l23);
    uint2 hv, lv;
    hv.x = *(uint32_t*)&h01; hv.y = *(uint32_t*)&h23;
    lv.x = *(uint32_t*)&l01; lv.y = *(uint32_t*)&l23;
    *(uint2*)(xnh + (size_t)row * 512 + tid * 4) = hv;
    *(uint2*)(xnl + (size_t)row * 512 + tid * 4) = lv;
}

// ---------------- layernorm over 128: un fp32 in place + unT split ----------
__global__ void ln128(float* __restrict__ u, bf16* __restrict__ uTh,
                      bf16* __restrict__ uTl,
                      const float* __restrict__ g, const float* __restrict__ b)
{
    const int warp = threadIdx.x >> 5, lane = threadIdx.x & 31;
    const int row  = blockIdx.x * 8 + warp;
    float4 v = ((const float4*)(u + (size_t)row * 128))[lane];
    float s  = v.x + v.y + v.z + v.w;
    float sq = v.x * v.x + v.y * v.y + v.z * v.z + v.w * v.w;
#pragma unroll
    for (int o = 16; o; o >>= 1) {
        s  += __shfl_xor_sync(0xffffffffu, s, o);
        sq += __shfl_xor_sync(0xffffffffu, sq, o);
    }
    const float mean = s * (1.f / 128.f);
    const float var  = sq * (1.f / 128.f) - mean * mean;
    const float rs   = rsqrtf(var + 1e-5f);
    float4 gv = ((const float4*)g)[lane], bv = ((const float4*)b)[lane];
    float4 o4;
    o4.x = (v.x - mean) * rs * gv.x + bv.x;
    o4.y = (v.y - mean) * rs * gv.y + bv.y;
    o4.z = (v.z - mean) * rs * gv.z + bv.z;
    o4.w = (v.w - mean) * rs * gv.w + bv.w;
    ((float4*)(u + (size_t)row * 128))[lane] = o4;
    const int bb = row >> 13, l = row & 8191;
    const size_t tbase = (size_t)bb * 128 * 8192 + l;
    const int h = lane * 4;
    float vals[4] = {o4.x, o4.y, o4.z, o4.w};
#pragma unroll
    for (int k = 0; k < 4; k++) {
        bf16 hh = __float2bfloat16(vals[k]);
        uTh[tbase + (size_t)(h + k) * 8192] = hh;
        uTl[tbase + (size_t)(h + k) * 8192] = __float2bfloat16(vals[k] - __bfloat162float(hh));
    }
}

// ---------------- DSS tables (split + concatenated Ahat') --------------------
__global__ void dss_tables(const float* __restrict__ lam_re, const float* __restrict__ lam_im,
                           const float* __restrict__ C_re, const float* __restrict__ C_im,
                           bf16* ArTRh, bf16* ArTRl, bf16* ArTIh, bf16* ArTIl,
                           bf16* AhCh, bf16* AhCl,
                           float* __restrict__ abar_re, float* __restrict__ abar_im,
                           float* __restrict__ cre, float* __restrict__ cim)
{
    const int n = blockIdx.x * 128 + threadIdx.x;
    if (n >= DST) return;
    const float lre = -expf(lam_re[n]);
    const float lim =  expf(lam_im[n]);
    const float mag = expf(lre);
    const float er = mag * cosf(lim), ei = mag * sinf(lim);
    const float den = lre * lre + lim * lim;
    const float nr = er - 1.f, ni = ei;
    const float wr = (nr * lre + ni * lim) / den;
    const float wi = (ni * lre - nr * lim) / den;
    for (int h = 0; h < DHID; h++) {
        const float a = C_re[h * DST + n], b = C_im[h * DST + n];
        cre[h * DST + n] = a * wr - b * wi;
        cim[h * DST + n] = a * wi + b * wr;
    }
    for (int t = 0; t < TCH; t++) {
        const float x1 = (float)(TCH - 1 - t);
        const float m1 = expf(x1 * lre);
        const float vr = m1 * cosf(x1 * lim), vi = m1 * sinf(x1 * lim);
        bf16 hr = __float2bfloat16(vr);
        ArTRh[n * TCH + t] = hr;
        ArTRl[n * TCH + t] = __float2bfloat16(vr - __bfloat162float(hr));
        bf16 hi = __float2bfloat16(vi);
        ArTIh[n * TCH + t] = hi;
        ArTIl[n * TCH + t] = __float2bfloat16(vi - __bfloat162float(hi));
        const float x2 = (float)(t + 1);
        const float m2 = expf(x2 * lre);
        const float wr2 = m2 * cosf(x2 * lim);
        const float wi2 = -m2 * sinf(x2 * lim);     // negated for [AhR | -AhI]
        bf16 h2 = __float2bfloat16(wr2);
        AhCh[t * 1024 + n] = h2;
        AhCl[t * 1024 + n] = __float2bfloat16(wr2 - __bfloat162float(h2));
        bf16 h3 = __float2bfloat16(wi2);
        AhCh[t * 1024 + 512 + n] = h3;
        AhCl[t * 1024 + 512 + n] = __float2bfloat16(wi2 - __bfloat162float(h3));
    }
    const float m3 = expf((float)TCH * lre);
    abar_re[n] = m3 * cosf((float)TCH * lim);
    abar_im[n] = m3 * sinf((float)TCH * lim);
}

// kern_chunk[d,h] = Re( sum_n c[h,n] exp(d*lam_n) )
__global__ void kernchunk(const float* __restrict__ lam_re, const float* __restrict__ lam_im,
                          const float* __restrict__ cre, const float* __restrict__ cim,
                          float* __restrict__ kc)
{
    const int d = blockIdx.x, h = threadIdx.x;   // <<<128,128>>>
    __shared__ float er[DST], ei[DST];
    for (int n = h; n < DST; n += 128) {
        const float lre = -expf(lam_re[n]);
        const float lim =  expf(lam_im[n]);
        const float m = expf((float)d * lre);
        er[n] = m * cosf((float)d * lim);
        ei[n] = m * sinf((float)d * lim);
    }
    __syncthreads();
    float s = 0.f;
    for (int n = 0; n < DST; n++)
        s += cre[h * DST + n] * er[n] - cim[h * DST + n] * ei[n];
    kc[d * DHID + h] = s;
}

// ---------------- chunk scan: fp32 Z in, concatenated split-bf16 P out ------
__global__ void scan_kernel(const float* __restrict__ Zre, const float* __restrict__ Zim,
                            bf16* __restrict__ Pch, bf16* __restrict__ Pcl,
                            const float* __restrict__ cre, const float* __restrict__ cim,
                            const float* __restrict__ abr, const float* __restrict__ abi)
{
    const int t = blockIdx.x * 256 + threadIdx.x;   // [0, 262144)
    const int n = t & 511, h = (t >> 9) & 127, b = t >> 16;
    const float ar = abr[n], ai = abi[n];
    const float kr = cre[h * DST + n], ki = cim[h * DST + n];
    float Sr = 0.f, Si = 0.f;
    const size_t stride  = (size_t)DHID * DST;
    const size_t stride2 = (size_t)DHID * 1024;
    size_t idx  = ((size_t)b * CCH * DHID + h) * DST + n;
    size_t idx2 = ((size_t)b * CCH * DHID + h) * 1024 + n;
    for (int c = 0; c < CCH; c++) {
        const float zr = Zre[idx], zi = Zim[idx];
        const float pr = kr * Sr - ki * Si;
        const float pi = kr * Si + ki * Sr;
        bf16 ph = __float2bfloat16(pr);
        Pch[idx2] = ph; Pcl[idx2] = __float2bfloat16(pr - __bfloat162float(ph));
        bf16 qh = __float2bfloat16(pi);
        Pch[idx2 + 512] = qh; Pcl[idx2 + 512] = __float2bfloat16(pi - __bfloat162float(qh));
        const float t1 = ar * Sr - ai * Si + zr;
        Si = ar * Si + ai * Sr + zi;
        Sr = t1;
        idx += stride; idx2 += stride2;
    }
}

// ---------------- intra-chunk conv + skip; writes split y --------------------
__global__ void intra_kernel(const float* __restrict__ un, const float* __restrict__ kc,
                             const float* __restrict__ y, const float* __restrict__ Ds,
                             bf16* __restrict__ yh, bf16* __restrict__ yl)
{
    extern __shared__ float sm[];
    float* Uc = sm;
    float* Kc = sm + TCH * DHID;
    const size_t base = (size_t)blockIdx.x * TCH * DHID;
    for (int i = threadIdx.x; i < TCH * DHID / 4; i += 256) {
        ((float4*)Uc)[i] = ((const float4*)(un + base))[i];
        ((float4*)Kc)[i] = ((const float4*)kc)[i];
    }
    __syncthreads();
    for (int e = threadIdx.x; e < TCH * DHID; e += 256) {
        const int dt = e >> 7, h = e & 127;
        float s = Uc[dt * DHID + h] * Ds[h] + y[base + e];
        for (int j = 0; j <= dt; j++)
            s = fmaf(Kc[(dt - j) * DHID + h], Uc[j * DHID + h], s);
        bf16 hh = __float2bfloat16(s);
        yh[base + e] = hh;
        yl[base + e] = __float2bfloat16(s - __bfloat162float(hh));
    }
}

// ---------------- generic fp32 -> bf16 hi/lo split ---------------------------
__global__ void fsplit(const float* __restrict__ s, bf16* __restrict__ h,
                       bf16* __restrict__ l, int n)
{
    const int i = blockIdx.x * 256 + threadIdx.x;
    if (i >= n) return;
    const float v = s[i];
    bf16 hh = __float2bfloat16(v);
    h[i] = hh;
    l[i] = __float2bfloat16(v - __bfloat162float(hh));
}

// ---------------- launch ----------------------------------------------------
extern "C" void kernel_launch(void* const* d_in, const int* in_sizes, int n_in,
                              void* d_out, int out_size)
{
    const float* x      = (const float*)d_in[0];
    const float* norm_g = (const float*)d_in[1];
    const float* norm_b = (const float*)d_in[2];
    const float* W_v    = (const float*)d_in[3];
    const float* W_u    = (const float*)d_in[4];
    const float* W_uc   = (const float*)d_in[5];
    const float* W_o    = (const float*)d_in[6];
    const float* b_o    = (const float*)d_in[7];
    const float* dss_g  = (const float*)d_in[8];
    const float* dss_b  = (const float*)d_in[9];
    const float* lam_re = (const float*)d_in[10];
    const float* lam_im = (const float*)d_in[11];
    const float* C_re   = (const float*)d_in[12];
    const float* C_im   = (const float*)d_in[13];
    const float* D_skip = (const float*)d_in[14];
    float* out = (float*)d_out;

    float *v, *un, *y, *Zre, *Zim, *abr, *abi, *cre, *cim, *kc;
    bf16 *xnh, *xnl, *unTh, *unTl, *Pch, *Pcl, *yh, *yl, *gvh, *gvl;
    bf16 *Wvh, *Wvl, *Wuh, *Wul, *Wuch, *Wucl, *Woh, *Wol;
    bf16 *ArTRh, *ArTRl, *ArTIh, *ArTIl, *AhCh, *AhCl;
    cudaGetSymbolAddress((void**)&v,   g_v);
    cudaGetSymbolAddress((void**)&un,  g_un);
    cudaGetSymbolAddress((void**)&y,   g_y);
    cudaGetSymbolAddress((void**)&Zre, g_Zre);
    cudaGetSymbolAddress((void**)&Zim, g_Zim);
    cudaGetSymbolAddress((void**)&abr, g_abar_re);
    cudaGetSymbolAddress((void**)&abi, g_abar_im);
    cudaGetSymbolAddress((void**)&cre, g_cre);
    cudaGetSymbolAddress((void**)&cim, g_cim);
    cudaGetSymbolAddress((void**)&kc,  g_kc);
    cudaGetSymbolAddress((void**)&xnh, g_xnh);
    cudaGetSymbolAddress((void**)&xnl, g_xnl);
    cudaGetSymbolAddress((void**)&unTh, g_unTh);
    cudaGetSymbolAddress((void**)&unTl, g_unTl);
    cudaGetSymbolAddress((void**)&Pch, g_Pch);
    cudaGetSymbolAddress((void**)&Pcl, g_Pcl);
    cudaGetSymbolAddress((void**)&yh,  g_yh);
    cudaGetSymbolAddress((void**)&yl,  g_yl);
    cudaGetSymbolAddress((void**)&gvh, g_gvh);
    cudaGetSymbolAddress((void**)&gvl, g_gvl);
    cudaGetSymbolAddress((void**)&Wvh, g_Wvh);
    cudaGetSymbolAddress((void**)&Wvl, g_Wvl);
    cudaGetSymbolAddress((void**)&Wuh, g_Wuh);
    cudaGetSymbolAddress((void**)&Wul, g_Wul);
    cudaGetSymbolAddress((void**)&Wuch, g_Wuch);
    cudaGetSymbolAddress((void**)&Wucl, g_Wucl);
    cudaGetSymbolAddress((void**)&Woh, g_Woh);
    cudaGetSymbolAddress((void**)&Wol, g_Wol);
    cudaGetSymbolAddress((void**)&ArTRh, g_ArTRh);
    cudaGetSymbolAddress((void**)&ArTRl, g_ArTRl);
    cudaGetSymbolAddress((void**)&ArTIh, g_ArTIh);
    cudaGetSymbolAddress((void**)&ArTIl, g_ArTIl);
    cudaGetSymbolAddress((void**)&AhCh, g_AhCh);
    cudaGetSymbolAddress((void**)&AhCl, g_AhCl);

    cudaFuncSetAttribute(tgemm<EPI_STORE>, cudaFuncAttributeMaxDynamicSharedMemorySize, TG_SMEM);
    cudaFuncSetAttribute(tgemm<EPI_GELU>,  cudaFuncAttributeMaxDynamicSharedMemorySize, TG_SMEM);
    cudaFuncSetAttribute(tgemm<EPI_FINAL>, cudaFuncAttributeMaxDynamicSharedMemorySize, TG_SMEM);
    cudaFuncSetAttribute(tgemm<EPI_MULSPLIT>, cudaFuncAttributeMaxDynamicSharedMemorySize, TG_SMEM);

    // 0) split weights (bf16 hi/lo)
    fsplit<<<(DGATE * DIN + 255) / 256, 256>>>(W_v, Wvh, Wvl, DGATE * DIN);
    fsplit<<<(DHID * DIN + 255) / 256, 256>>>(W_u, Wuh, Wul, DHID * DIN);
    fsplit<<<(DGATE * DHID + 255) / 256, 256>>>(W_uc, Wuch, Wucl, DGATE * DHID);
    fsplit<<<(DIN * DGATE + 255) / 256, 256>>>(W_o, Woh, Wol, DIN * DGATE);

    // 1) xn = LN(x) -> split
    ln512<<<MROWS, 128>>>(x, norm_g, norm_b, xnh, xnl);

    // 2) v = gelu(xn @ W_v^T)   [32768 x 2048] fp32
    tgemm<EPI_GELU><<<dim3(DGATE / 128, MROWS / 128, 1), 256, TG_SMEM>>>(
        DIN, xnh, xnl, DIN, 0, 0, Wvh, Wvl, DIN, 0, 0,
        v, DGATE, 0, 0, 1, nullptr, nullptr, nullptr, nullptr);

    // 3) u = gelu(xn @ W_u^T)   [32768 x 128] fp32
    tgemm<EPI_GELU><<<dim3(1, MROWS / 128, 1), 256, TG_SMEM>>>(
        DIN, xnh, xnl, DIN, 0, 0, Wuh, Wul, DIN, 0, 0,
        un, DHID, 0, 0, 1, nullptr, nullptr, nullptr, nullptr);

    // 4) un = LN(u) fp32 in place; unT split
    ln128<<<MROWS / 8, 256>>>(un, unTh, unTl, dss_g, dss_b);

    // 5) DSS tables
    dss_tables<<<DST / 128, 128>>>(lam_re, lam_im, C_re, C_im,
                                   ArTRh, ArTRl, ArTIh, ArTIl,
                                   AhCh, AhCl, abr, abi, cre, cim);
    kernchunk<<<TCH, DHID>>>(lam_re, lam_im, cre, cim, kc);

    // 6) Z[b,c,h,n] = sum_t unT[b,h,cT+t] * ArevT[n,t]   fp32 out
    tgemm<EPI_STORE><<<dim3(DST / 128, 1, BSZ * CCH), 256, TG_SMEM>>>(
        TCH, unTh, unTl, LSEQ, (long long)DHID * LSEQ, TCH,
        ArTRh, ArTRl, TCH, 0, 0,
        Zre, DST, (long long)CCH * DHID * DST, (long long)DHID * DST,
        CCH, nullptr, nullptr, nullptr, nullptr);
    tgemm<EPI_STORE><<<dim3(DST / 128, 1, BSZ * CCH), 256, TG_SMEM>>>(
        TCH, unTh, unTl, LSEQ, (long long)DHID * LSEQ, TCH,
        ArTIh, ArTIl, TCH, 0, 0,
        Zim, DST, (long long)CCH * DHID * DST, (long long)DHID * DST,
        CCH, nullptr, nullptr, nullptr, nullptr);

    // 7) scan across chunks; P = c * S_start, concatenated [Pre|Pim], split
    scan_kernel<<<(BSZ * DHID * DST) / 256, 256>>>(Zre, Zim, Pch, Pcl,
                                                   cre, cim, abr, abi);

    // 8) y_inter = [AhR | -AhI] @ [Pre | Pim]^T, single K=1024 GEMM
    tgemm<EPI_STORE><<<dim3(1, 1, BSZ * CCH), 256, TG_SMEM>>>(
        1024, AhCh, AhCl, 1024, 0, 0,
        Pch, Pcl, 1024, (long long)CCH * DHID * 1024, (long long)DHID * 1024,
        y, DHID, (long long)CCH * TCH * DHID, (long long)TCH * DHID,
        CCH, nullptr, nullptr, nullptr, nullptr);

    // 9) y += intra conv + skip; write split y
    cudaFuncSetAttribute(intra_kernel, cudaFuncAttributeMaxDynamicSharedMemorySize,
                         2 * TCH * DHID * (int)sizeof(float));
    intra_kernel<<<BSZ * CCH, 256, 2 * TCH * DHID * sizeof(float)>>>(un, kc, y, D_skip, yh, yl);

    // 10) gv = (y @ W_uc^T) * v  -> split bf16
    tgemm<EPI_MULSPLIT><<<dim3(DGATE / 128, MROWS / 128, 1), 256, TG_SMEM>>>(
        DHID, yh, yl, DHID, 0, 0, Wuch, Wucl, DHID, 0, 0,
        v, DGATE, 0, 0, 1, nullptr, nullptr, gvh, gvl);

    // 11) out = gv @ W_o^T + b_o + x
    tgemm<EPI_FINAL><<<dim3(DIN / 128, MROWS / 128, 1), 256, TG_SMEM>>>(
        DGATE, gvh, gvl, DGATE, 0, 0, Woh, Wol, DGATE, 0, 0,
        out, DIN, 0, 0, 1, b_o, x, nullptr, nullptr);
}

// round 7
// speedup vs baseline: 3.3650x; 1.2144x over previous
#include <cuda_runtime.h>
#include <cuda_bf16.h>
#include <cuda_fp16.h>
#include <cstdint>
#include <math.h>

// Problem dims
#define BSZ   4
#define LSEQ  8192
#define DIN   512
#define DGATE 2048
#define DHID  128
#define DST   512
#define TCH   128
#define CCH   64
#define MROWS (BSZ*LSEQ)   // 32768
#define NCAT  (DGATE + DHID)   // 2176 fused v+u columns

typedef __nv_bfloat16 bf16;
typedef __nv_bfloat162 bf162;

// ---------------- scratch (static device globals; no runtime alloc) --------
__device__ float g_v   [(size_t)MROWS*DGATE];
__device__ float g_un  [(size_t)MROWS*DHID];
__device__ float g_y   [(size_t)MROWS*DHID];
__device__ float g_Zc  [(size_t)BSZ*CCH*DHID*1024];   // concat [Zre|Zim]
__device__ float g_abar_re [DST];
__device__ float g_abar_im [DST];
__device__ float g_cre     [DHID*DST];
__device__ float g_cim     [DHID*DST];
__device__ float g_kc      [TCH*DHID];
// fp16 operands (2-term GEMMs)
__device__ __half g_xnh [(size_t)MROWS*DIN];
__device__ __half g_xnl [(size_t)MROWS*DIN];
__device__ __half g_gvh [(size_t)MROWS*DGATE];
__device__ __half g_gvl [(size_t)MROWS*DGATE];
__device__ __half g_Wcat16[(size_t)NCAT*DIN];         // [Wv; Wu] rounded
__device__ __half g_Wo16  [(size_t)DIN*DGATE];
// bf16 split operands (3-term GEMMs)
__device__ bf16 g_unTh[(size_t)BSZ*DHID*LSEQ];
__device__ bf16 g_unTl[(size_t)BSZ*DHID*LSEQ];
__device__ bf16 g_Pch [(size_t)BSZ*CCH*DHID*1024];    // concat [Pre|Pim]
__device__ bf16 g_Pcl [(size_t)BSZ*CCH*DHID*1024];
__device__ bf16 g_yh  [(size_t)MROWS*DHID];
__device__ bf16 g_yl  [(size_t)MROWS*DHID];
__device__ bf16 g_Wuch[DGATE*DHID], g_Wucl[DGATE*DHID];
__device__ bf16 g_ArCh[1024*TCH], g_ArCl[1024*TCH];   // concat [ArevT_re; ArevT_im]
__device__ bf16 g_AhCh[TCH*1024], g_AhCl[TCH*1024];   // concat [AhR | -AhI]

// ---------------- helpers ---------------------------------------------------
__device__ __forceinline__ float gelu_exact(float x) {
    return 0.5f * x * (1.0f + erff(x * 0.70710678118654752440f));
}
__device__ __forceinline__ uint32_t smem_u32(const void* p) {
    uint32_t a;
    asm("{ .reg .u64 t; cvta.to.shared.u64 t, %1; cvt.u32.u64 %0, t; }"
        : "=r"(a) : "l"(p));
    return a;
}
__device__ __forceinline__ void ldm_x4(uint32_t* r, uint32_t addr) {
    asm volatile("ldmatrix.sync.aligned.m8n8.x4.shared.b16 {%0,%1,%2,%3}, [%4];"
        : "=r"(r[0]), "=r"(r[1]), "=r"(r[2]), "=r"(r[3]) : "r"(addr));
}
__device__ __forceinline__ void mma_bf16(float* d, const uint32_t* a, const uint32_t* b) {
    asm volatile(
        "mma.sync.aligned.m16n8k16.row.col.f32.bf16.bf16.f32 "
        "{%0,%1,%2,%3}, {%4,%5,%6,%7}, {%8,%9}, {%0,%1,%2,%3};"
        : "+f"(d[0]), "+f"(d[1]), "+f"(d[2]), "+f"(d[3])
        : "r"(a[0]), "r"(a[1]), "r"(a[2]), "r"(a[3]), "r"(b[0]), "r"(b[1]));
}
__device__ __forceinline__ void mma_f16(float* d, const uint32_t* a, const uint32_t* b) {
    asm volatile(
        "mma.sync.aligned.m16n8k16.row.col.f32.f16.f16.f32 "
        "{%0,%1,%2,%3}, {%4,%5,%6,%7}, {%8,%9}, {%0,%1,%2,%3};"
        : "+f"(d[0]), "+f"(d[1]), "+f"(d[2]), "+f"(d[3])
        : "r"(a[0]), "r"(a[1]), "r"(a[2]), "r"(a[3]), "r"(b[0]), "r"(b[1]));
}
__device__ __forceinline__ void cpasync16(uint32_t dst, const void* src) {
    asm volatile("cp.async.cg.shared.global [%0], [%1], 16;" :: "r"(dst), "l"(src));
}
__device__ __forceinline__ void bsplit2(float a, float b, bf162& h, bf162& l) {
    h = __floats2bfloat162_rn(a, b);
    l = __floats2bfloat162_rn(a - __bfloat162float(h.x), b - __bfloat162float(h.y));
}

enum { EPI_STORE = 0, EPI_GELU2 = 1, EPI_FINAL = 4, EPI_MULSPLIT = 5 };

// smem: per stage, up to 4 buffers (Ahi,Alo,Bhi,Blo) of 128 rows x (64B+16B pad)
#define ROWB    80
#define BUFB    (128 * ROWB)     // 10240
#define STAGEB  (4 * BUFB)       // 40960
#define TG_SMEM (2 * STAGEB)     // 81920

// ---------------- tensor GEMM, cp.async double-buffered ---------------------
// C = A(MxK) * B(NxK)^T. MODE 0: bf16x3 (A,B both hi/lo). MODE 1: fp16x2
// (A hi/lo, B single). 128x128 CTA tile, 8 warps, K chunks of 32.
template <int EPI, int MODE>
__global__ __launch_bounds__(256, 2)
void tgemm(int K,
           const uint16_t* __restrict__ Ah, const uint16_t* __restrict__ Al,
           int lda, long long sAb, long long sAc,
           const uint16_t* __restrict__ Bh, const uint16_t* __restrict__ Bl,
           int ldb, long long sBb, long long sBc,
           float* __restrict__ C, int ldc, long long sCb, long long sCc,
           int CB,
           const float* __restrict__ bias, const float* __restrict__ resid,
           float* __restrict__ C2,
           __half* __restrict__ Oh, __half* __restrict__ Ol)
{
    extern __shared__ __align__(16) char smem[];
    const uint32_t sbase = smem_u32(smem);

    const int tid  = threadIdx.x;
    const int wid  = tid >> 5;
    const int lane = tid & 31;
    const int wm   = wid & 3;
    const int wn   = wid >> 2;

    const int zb = blockIdx.z / CB, zc = blockIdx.z % CB;
    Ah += (size_t)zb * sAb + (size_t)zc * sAc;
    Al += (size_t)zb * sAb + (size_t)zc * sAc;
    Bh += (size_t)zb * sBb + (size_t)zc * sBc;
    Bl += (size_t)zb * sBb + (size_t)zc * sBc;
    C  += (size_t)zb * sCb + (size_t)zc * sCc;
    const int row0 = blockIdx.y * 128;
    const int col0 = blockIdx.x * 128;

    const int lrow = (tid >> 2) & 63;
    const int lc16 = tid & 3;
    const uint32_t sdst0 = (uint32_t)(lrow * ROWB + lc16 * 16);

    float acc[2][8][4];
#pragma unroll
    for (int i = 0; i < 2; i++)
#pragma unroll
        for (int j = 0; j < 8; j++)
#pragma unroll
            for (int k = 0; k < 4; k++) acc[i][j][k] = 0.f;

    const uint32_t aOff = (uint32_t)((wm * 32 + (lane & 15)) * ROWB + ((lane & 16) ? 16 : 0));
    const uint32_t bOff = (uint32_t)(2 * BUFB +
        (wn * 64 + (lane & 7) + ((lane & 16) ? 8 : 0)) * ROWB + ((lane & 8) ? 16 : 0));

    const int nchunk = K >> 5;

    auto issue = [&](int st, int k0) {
        const uint32_t sb = sbase + st * STAGEB;
#pragma unroll
        for (int i = 0; i < 8; i++) {
            const int buf = i >> 1;
            if (MODE == 1 && buf == 3) continue;      // no Blo in fp16x2
            const int row  = (i & 1) * 64 + lrow;
            const int eoff = k0 + lc16 * 8;
            const uint16_t* src;
            if      (buf == 0) src = Ah + (size_t)(row0 + row) * lda + eoff;
            else if (buf == 1) src = Al + (size_t)(row0 + row) * lda + eoff;
            else if (buf == 2) src = Bh + (size_t)(col0 + row) * ldb + eoff;
            else               src = Bl + (size_t)(col0 + row) * ldb + eoff;
            cpasync16(sb + buf * BUFB + (i & 1) * (64 * ROWB) + sdst0, src);
        }
        asm volatile("cp.async.commit_group;" ::: "memory");
    };

    issue(0, 0);

    for (int c = 0; c < nchunk; c++) {
        asm volatile("cp.async.wait_group 0;" ::: "memory");
        __syncthreads();
        if (c + 1 < nchunk) issue((c + 1) & 1, (c + 1) << 5);

        const uint32_t sb = sbase + (c & 1) * STAGEB;
#pragma unroll
        for (int k16 = 0; k16 < 2; k16++) {
            uint32_t ahi[2][4], alo[2][4];
#pragma unroll
            for (int mt = 0; mt < 2; mt++) {
                const uint32_t aa = sb + aOff + mt * (16 * ROWB) + k16 * 32;
                ldm_x4(ahi[mt], aa);
                ldm_x4(alo[mt], aa + BUFB);
            }
#pragma unroll
            for (int p = 0; p < 4; p++) {
                const uint32_t ba = sb + bOff + p * (16 * ROWB) + k16 * 32;
                uint32_t bhi[4];
                ldm_x4(bhi, ba);
                uint32_t blo[4];
                if (MODE == 0) ldm_x4(blo, ba + BUFB);
#pragma unroll
                for (int mt = 0; mt < 2; mt++) {
#pragma unroll
                    for (int hh = 0; hh < 2; hh++) {
                        float* d = acc[mt][p * 2 + hh];
                        if (MODE == 0) {
                            mma_bf16(d, ahi[mt], &bhi[hh * 2]);
                            mma_bf16(d, ahi[mt], &blo[hh * 2]);
                            mma_bf16(d, alo[mt], &bhi[hh * 2]);
                        } else {
                            mma_f16(d, ahi[mt], &bhi[hh * 2]);
                            mma_f16(d, alo[mt], &bhi[hh * 2]);
                        }
                    }
                }
            }
        }
    }

    // ---- epilogue ----
    const int qrow = lane >> 2, qcol = (lane & 3) * 2;
#pragma unroll
    for (int mt = 0; mt < 2; mt++) {
#pragma unroll
        for (int nt = 0; nt < 8; nt++) {
            const int r0r = row0 + wm * 32 + mt * 16 + qrow;
            const int cc  = col0 + wn * 64 + nt * 8 + qcol;
            float* d = acc[mt][nt];
#pragma unroll
            for (int h = 0; h < 2; h++) {
                const int rr = r0r + h * 8;
                const size_t idx = (size_t)rr * ldc + cc;
                float2 o = make_float2(d[h * 2 + 0], d[h * 2 + 1]);
                if (EPI == EPI_GELU2) {
                    o.x = gelu_exact(o.x); o.y = gelu_exact(o.y);
                    if (cc < DGATE) *(float2*)(C + idx) = o;
                    else *(float2*)(C2 + (size_t)rr * DHID + (cc - DGATE)) = o;
                } else if (EPI == EPI_FINAL) {
                    const float2 bb = *(const float2*)(bias + cc);
                    const float2 rr2 = *(const float2*)(resid + idx);
                    o.x += bb.x + rr2.x; o.y += bb.y + rr2.y;
                    *(float2*)(C + idx) = o;
                } else if (EPI == EPI_MULSPLIT) {
                    const float2 q = *(const float2*)(C + idx);   // gate v (fp32)
                    o.x *= q.x; o.y *= q.y;
                    __half2 hh2 = __floats2half2_rn(o.x, o.y);
                    float lx = o.x - __low2float(hh2);
                    float ly = o.y - __high2float(hh2);
                    *(__half2*)(Oh + idx) = hh2;
                    *(__half2*)(Ol + idx) = __floats2half2_rn(lx, ly);
                } else {  // EPI_STORE
                    *(float2*)(C + idx) = o;
                }
            }
        }
    }
}

// ---------------- layernorm over 512 -> split fp16 --------------------------
__global__ void ln512(const float* __restrict__ x, const float* __restrict__ g,
                      const float* __restrict__ b,
                      __half* __restrict__ xnh, __half* __restrict__ xnl)
{
    const int row = blockIdx.x, tid = threadIdx.x;  // 128 threads
    float4 v = ((const float4*)(x + (size_t)row * 512))[tid];
    float s  = v.x + v.y + v.z + v.w;
    float sq = v.x * v.x + v.y * v.y + v.z * v.z + v.w * v.w;
#pragma unroll
    for (int o = 16; o; o >>= 1) {
        s  += __shfl_xor_sync(0xffffffffu, s, o);
        sq += __shfl_xor_sync(0xffffffffu, sq, o);
    }
    __shared__ float ss[4], ssq[4];
    if ((tid & 31) == 0) { ss[tid >> 5] = s; ssq[tid >> 5] = sq; }
    __syncthreads();
    s  = ss[0] + ss[1] + ss[2] + ss[3];
    sq = ssq[0] + ssq[1] + ssq[2] + ssq[3];
    const float mean = s * (1.f / 512.f);
    const float var  = sq * (1.f / 512.f) - mean * mean;
    const float rs   = rsqrtf(var + 1e-5f);
    float4 gv = ((const float4*)g)[tid], bv = ((const float4*)b)[tid];
    float4 o4;
    o4.x = (v.x - mean) * rs * gv.x + bv.x;
    o4.y = (v.y - mean) * rs * gv.y + bv.y;
    o4.z = (v.z - mean) * rs * gv.z + bv.z;
    o4.w = (v.w - mean) * rs * gv.w + bv.w;
    __half2 h01 = __floats2half2_rn(o4.x, o4.y);
    __half2 h23 = __floats2half2_rn(o4.z, o4.w);
    __half2 l01 = __floats2half2_rn(o4.x - __low2float(h01), o4.y - __high2float(h01));
    __half2 l23 = __floats2half2_rn(o4.z - __low2float(h23), o4.w - __high2float(h23));
    uint2 hv, lv;
    hv.x = *(uint32_t*)&h01; hv.y = *(uint32_t*)&h23;
    lv.x = *(uint32_t*)&l01; lv.y = *(uint32_t*)&l23;
    *(uint2*)(xnh + (size_t)row * 512 + tid * 4) = hv;
    *(uint2*)(xnl + (size_t)row * 512 + tid * 4) = lv;
}

// ---------------- layernorm over 128: un fp32 in place + unT split bf16 -----
__global__ void ln128(float* __restrict__ u, bf16* __restrict__ uTh,
                      bf16* __restrict__ uTl,
                      const float* __restrict__ g, const float* __restrict__ b)
{
    const int warp = threadIdx.x >> 5, lane = threadIdx.x & 31;
    const int row  = blockIdx.x * 8 + warp;
    float4 v = ((const float4*)(u + (size_t)row * 128))[lane];
    float s  = v.x + v.y + v.z + v.w;
    float sq = v.x * v.x + v.y * v.y + v.z * v.z + v.w * v.w;
#pragma unroll
    for (int o = 16; o; o >>= 1) {
        s  += __shfl_xor_sync(0xffffffffu, s, o);
        sq += __shfl_xor_sync(0xffffffffu, sq, o);
    }
    const float mean = s * (1.f / 128.f);
    const float var  = sq * (1.f / 128.f) - mean * mean;
    const float rs   = rsqrtf(var + 1e-5f);
    float4 gv = ((const float4*)g)[lane], bv = ((const float4*)b)[lane];
    float4 o4;
    o4.x = (v.x - mean) * rs * gv.x + bv.x;
    o4.y = (v.y - mean) * rs * gv.y + bv.y;
    o4.z = (v.z - mean) * rs * gv.z + bv.z;
    o4.w = (v.w - mean) * rs * gv.w + bv.w;
    ((float4*)(u + (size_t)row * 128))[lane] = o4;
    const int bb = row >> 13, l = row & 8191;
    const size_t tbase = (size_t)bb * 128 * 8192 + l;
    const int h = lane * 4;
    float vals[4] = {o4.x, o4.y, o4.z, o4.w};
#pragma unroll
    for (int k = 0; k < 4; k++) {
        bf16 hh = __float2bfloat16(vals[k]);
        uTh[tbase + (size_t)(h + k) * 8192] = hh;
        uTl[tbase + (size_t)(h + k) * 8192] = __float2bfloat16(vals[k] - __bfloat162float(hh));
    }
}

// ---------------- DSS tables --------------------------------------------------
__global__ void dss_tables(const float* __restrict__ lam_re, const float* __restrict__ lam_im,
                           const float* __restrict__ C_re, const float* __restrict__ C_im,
                           bf16* ArCh, bf16* ArCl, bf16* AhCh, bf16* AhCl,
                           float* __restrict__ abar_re, float* __restrict__ abar_im,
                           float* __restrict__ cre, float* __restrict__ cim)
{
    const int n = blockIdx.x * 128 + threadIdx.x;
    if (n >= DST) return;
    const float lre = -expf(lam_re[n]);
    const float lim =  expf(lam_im[n]);
    const float mag = expf(lre);
    const float er = mag * cosf(lim), ei = mag * sinf(lim);
    const float den = lre * lre + lim * lim;
    const float nr = er - 1.f, ni = ei;
    const float wr = (nr * lre + ni * lim) / den;
    const float wi = (ni * lre - nr * lim) / den;
    for (int h = 0; h < DHID; h++) {
        const float a = C_re[h * DST + n], b = C_im[h * DST + n];
        cre[h * DST + n] = a * wr - b * wi;
        cim[h * DST + n] = a * wi + b * wr;
    }
    for (int t = 0; t < TCH; t++) {
        const float x1 = (float)(TCH - 1 - t);
        const float m1 = expf(x1 * lre);
        const float vr = m1 * cosf(x1 * lim), vi = m1 * sinf(x1 * lim);
        bf16 hr = __float2bfloat16(vr);
        ArCh[n * TCH + t] = hr;
        ArCl[n * TCH + t] = __float2bfloat16(vr - __bfloat162float(hr));
        bf16 hi = __float2bfloat16(vi);
        ArCh[(512 + n) * TCH + t] = hi;
        ArCl[(512 + n) * TCH + t] = __float2bfloat16(vi - __bfloat162float(hi));
        const float x2 = (float)(t + 1);
        const float m2 = expf(x2 * lre);
        const float wr2 = m2 * cosf(x2 * lim);
        const float wi2 = -m2 * sinf(x2 * lim);     // negated for [AhR | -AhI]
        bf16 h2 = __float2bfloat16(wr2);
        AhCh[t * 1024 + n] = h2;
        AhCl[t * 1024 + n] = __float2bfloat16(wr2 - __bfloat162float(h2));
        bf16 h3 = __float2bfloat16(wi2);
        AhCh[t * 1024 + 512 + n] = h3;
        AhCl[t * 1024 + 512 + n] = __float2bfloat16(wi2 - __bfloat162float(h3));
    }
    const float m3 = expf((float)TCH * lre);
    abar_re[n] = m3 * cosf((float)TCH * lim);
    abar_im[n] = m3 * sinf((float)TCH * lim);
}

// kern_chunk[d,h] = Re( sum_n c[h,n] exp(d*lam_n) )
__global__ void kernchunk(const float* __restrict__ lam_re, const float* __restrict__ lam_im,
                          const float* __restrict__ cre, const float* __restrict__ cim,
                          float* __restrict__ kc)
{
    const int d = blockIdx.x, h = threadIdx.x;   // <<<128,128>>>
    __shared__ float er[DST], ei[DST];
    for (int n = h; n < DST; n += 128) {
        const float lre = -expf(lam_re[n]);
        const float lim =  expf(lam_im[n]);
        const float m = expf((float)d * lre);
        er[n] = m * cosf((float)d * lim);
        ei[n] = m * sinf((float)d * lim);
    }
    __syncthreads();
    float s = 0.f;
    for (int n = 0; n < DST; n++)
        s += cre[h * DST + n] * er[n] - cim[h * DST + n] * ei[n];
    kc[d * DHID + h] = s;
}

// ---------------- chunk scan: concat Z fp32 in, concat split-bf16 P out -----
__global__ void scan_kernel(const float* __restrict__ Zc,
                            bf16* __restrict__ Pch, bf16* __restrict__ Pcl,
                            const float* __restrict__ cre, const float* __restrict__ cim,
                            const float* __restrict__ abr, const float* __restrict__ abi)
{
    const int t = blockIdx.x * 256 + threadIdx.x;   // [0, 262144)
    const int n = t & 511, h = (t >> 9) & 127, b = t >> 16;
    const float ar = abr[n], ai = abi[n];
    const float kr = cre[h * DST + n], ki = cim[h * DST + n];
    float Sr = 0.f, Si = 0.f;
    const size_t stride = (size_t)DHID * 1024;
    size_t idx = ((size_t)b * CCH * DHID + h) * 1024 + n;
    for (int c = 0; c < CCH; c++) {
        const float zr = Zc[idx], zi = Zc[idx + 512];
        const float pr = kr * Sr - ki * Si;
        const float pi = kr * Si + ki * Sr;
        bf16 ph = __float2bfloat16(pr);
        Pch[idx] = ph; Pcl[idx] = __float2bfloat16(pr - __bfloat162float(ph));
        bf16 qh = __float2bfloat16(pi);
        Pch[idx + 512] = qh; Pcl[idx + 512] = __float2bfloat16(pi - __bfloat162float(qh));
        const float t1 = ar * Sr - ai * Si + zr;
        Si = ar * Si + ai * Sr + zi;
        Sr = t1;
        idx += stride;
    }
}

// ---------------- intra-chunk conv + skip; writes split bf16 y ---------------
__global__ void intra_kernel(const float* __restrict__ un, const float* __restrict__ kc,
                             const float* __restrict__ y, const float* __restrict__ Ds,
                             bf16* __restrict__ yh, bf16* __restrict__ yl)
{
    extern __shared__ float sm[];
    float* Uc = sm;
    float* Kc = sm + TCH * DHID;
    const size_t base = (size_t)blockIdx.x * TCH * DHID;
    for (int i = threadIdx.x; i < TCH * DHID / 4; i += 256) {
        ((float4*)Uc)[i] = ((const float4*)(un + base))[i];
        ((float4*)Kc)[i] = ((const float4*)kc)[i];
    }
    __syncthreads();
    for (int e = threadIdx.x; e < TCH * DHID; e += 256) {
        const int dt = e >> 7, h = e & 127;
        float s = Uc[dt * DHID + h] * Ds[h] + y[base + e];
        for (int j = 0; j <= dt; j++)
            s = fmaf(Kc[(dt - j) * DHID + h], Uc[j * DHID + h], s);
        bf16 hh = __float2bfloat16(s);
        yh[base + e] = hh;
        yl[base + e] = __float2bfloat16(s - __bfloat162float(hh));
    }
}

// ---------------- fp32 -> fp16 round / fp32 -> bf16 hi/lo split --------------
__global__ void fround16(const float* __restrict__ s, __half* __restrict__ d, int n)
{
    const int i = blockIdx.x * 256 + threadIdx.x;
    if (i < n) d[i] = __float2half_rn(s[i]);
}
__global__ void fsplit(const float* __restrict__ s, bf16* __restrict__ h,
                       bf16* __restrict__ l, int n)
{
    const int i = blockIdx.x * 256 + threadIdx.x;
    if (i >= n) return;
    const float v = s[i];
    bf16 hh = __float2bfloat16(v);
    h[i] = hh;
    l[i] = __float2bfloat16(v - __bfloat162float(hh));
}

// ---------------- launch ----------------------------------------------------
extern "C" void kernel_launch(void* const* d_in, const int* in_sizes, int n_in,
                              void* d_out, int out_size)
{
    const float* x      = (const float*)d_in[0];
    const float* norm_g = (const float*)d_in[1];
    const float* norm_b = (const float*)d_in[2];
    const float* W_v    = (const float*)d_in[3];
    const float* W_u    = (const float*)d_in[4];
    const float* W_uc   = (const float*)d_in[5];
    const float* W_o    = (const float*)d_in[6];
    const float* b_o    = (const float*)d_in[7];
    const float* dss_g  = (const float*)d_in[8];
    const float* dss_b  = (const float*)d_in[9];
    const float* lam_re = (const float*)d_in[10];
    const float* lam_im = (const float*)d_in[11];
    const float* C_re   = (const float*)d_in[12];
    const float* C_im   = (const float*)d_in[13];
    const float* D_skip = (const float*)d_in[14];
    float* out = (float*)d_out;

    float *v, *un, *y, *Zc, *abr, *abi, *cre, *cim, *kc;
    __half *xnh, *xnl, *gvh, *gvl, *Wcat16, *Wo16;
    bf16 *unTh, *unTl, *Pch, *Pcl, *yh, *yl, *Wuch, *Wucl, *ArCh, *ArCl, *AhCh, *AhCl;
    cudaGetSymbolAddress((void**)&v,   g_v);
    cudaGetSymbolAddress((void**)&un,  g_un);
    cudaGetSymbolAddress((void**)&y,   g_y);
    cudaGetSymbolAddress((void**)&Zc,  g_Zc);
    cudaGetSymbolAddress((void**)&abr, g_abar_re);
    cudaGetSymbolAddress((void**)&abi, g_abar_im);
    cudaGetSymbolAddress((void**)&cre, g_cre);
    cudaGetSymbolAddress((void**)&cim, g_cim);
    cudaGetSymbolAddress((void**)&kc,  g_kc);
    cudaGetSymbolAddress((void**)&xnh, g_xnh);
    cudaGetSymbolAddress((void**)&xnl, g_xnl);
    cudaGetSymbolAddress((void**)&gvh, g_gvh);
    cudaGetSymbolAddress((void**)&gvl, g_gvl);
    cudaGetSymbolAddress((void**)&Wcat16, g_Wcat16);
    cudaGetSymbolAddress((void**)&Wo16, g_Wo16);
    cudaGetSymbolAddress((void**)&unTh, g_unTh);
    cudaGetSymbolAddress((void**)&unTl, g_unTl);
    cudaGetSymbolAddress((void**)&Pch, g_Pch);
    cudaGetSymbolAddress((void**)&Pcl, g_Pcl);
    cudaGetSymbolAddress((void**)&yh,  g_yh);
    cudaGetSymbolAddress((void**)&yl,  g_yl);
    cudaGetSymbolAddress((void**)&Wuch, g_Wuch);
    cudaGetSymbolAddress((void**)&Wucl, g_Wucl);
    cudaGetSymbolAddress((void**)&ArCh, g_ArCh);
    cudaGetSymbolAddress((void**)&ArCl, g_ArCl);
    cudaGetSymbolAddress((void**)&AhCh, g_AhCh);
    cudaGetSymbolAddress((void**)&AhCl, g_AhCl);

    cudaFuncSetAttribute(tgemm<EPI_GELU2, 1>, cudaFuncAttributeMaxDynamicSharedMemorySize, TG_SMEM);
    cudaFuncSetAttribute(tgemm<EPI_STORE, 0>, cudaFuncAttributeMaxDynamicSharedMemorySize, TG_SMEM);
    cudaFuncSetAttribute(tgemm<EPI_MULSPLIT, 0>, cudaFuncAttributeMaxDynamicSharedMemorySize, TG_SMEM);
    cudaFuncSetAttribute(tgemm<EPI_FINAL, 1>, cudaFuncAttributeMaxDynamicSharedMemorySize, TG_SMEM);

    // 0) prep weights
    fround16<<<(DGATE * DIN + 255) / 256, 256>>>(W_v, Wcat16, DGATE * DIN);
    fround16<<<(DHID * DIN + 255) / 256, 256>>>(W_u, Wcat16 + (size_t)DGATE * DIN, DHID * DIN);
    fround16<<<(DIN * DGATE + 255) / 256, 256>>>(W_o, Wo16, DIN * DGATE);
    fsplit<<<(DGATE * DHID + 255) / 256, 256>>>(W_uc, Wuch, Wucl, DGATE * DHID);

    // 1) xn = LN(x) -> split fp16
    ln512<<<MROWS, 128>>>(x, norm_g, norm_b, xnh, xnl);

    // 2+3) [v | u] = gelu(xn @ [Wv; Wu]^T)  fused, fp16x2, N=2176
    tgemm<EPI_GELU2, 1><<<dim3(NCAT / 128, MROWS / 128, 1), 256, TG_SMEM>>>(
        DIN, (const uint16_t*)xnh, (const uint16_t*)xnl, DIN, 0, 0,
        (const uint16_t*)Wcat16, (const uint16_t*)Wcat16, DIN, 0, 0,
        v, DGATE, 0, 0, 1, nullptr, nullptr, un, nullptr, nullptr);

    // 4) un = LN(u) fp32 in place; unT split bf16
    ln128<<<MROWS / 8, 256>>>(un, unTh, unTl, dss_g, dss_b);

    // 5) DSS tables
    dss_tables<<<DST / 128, 128>>>(lam_re, lam_im, C_re, C_im,
                                   ArCh, ArCl, AhCh, AhCl, abr, abi, cre, cim);
    kernchunk<<<TCH, DHID>>>(lam_re, lam_im, cre, cim, kc);

    // 6) Zc[b,c,h,n2] = sum_t unT[b,h,cT+t] * ArC[n2,t]   (fused re|im, bf16x3)
    tgemm<EPI_STORE, 0><<<dim3(8, 1, BSZ * CCH), 256, TG_SMEM>>>(
        TCH, (const uint16_t*)unTh, (const uint16_t*)unTl, LSEQ,
        (long long)DHID * LSEQ, TCH,
        (const uint16_t*)ArCh, (const uint16_t*)ArCl, TCH, 0, 0,
        Zc, 1024, (long long)CCH * DHID * 1024, (long long)DHID * 1024,
        CCH, nullptr, nullptr, nullptr, nullptr, nullptr);

    // 7) scan across chunks; P = c * S_start, concat [Pre|Pim] split bf16
    scan_kernel<<<(BSZ * DHID * DST) / 256, 256>>>(Zc, Pch, Pcl, cre, cim, abr, abi);

    // 8) y_inter = [AhR | -AhI] @ P^T, single K=1024 GEMM (bf16x3)
    tgemm<EPI_STORE, 0><<<dim3(1, 1, BSZ * CCH), 256, TG_SMEM>>>(
        1024, (const uint16_t*)AhCh, (const uint16_t*)AhCl, 1024, 0, 0,
        (const uint16_t*)Pch, (const uint16_t*)Pcl, 1024,
        (long long)CCH * DHID * 1024, (long long)DHID * 1024,
        y, DHID, (long long)CCH * TCH * DHID, (long long)TCH * DHID,
        CCH, nullptr, nullptr, nullptr, nullptr, nullptr);

    // 9) y += intra conv + skip; write split bf16 y
    cudaFuncSetAttribute(intra_kernel, cudaFuncAttributeMaxDynamicSharedMemorySize,
                         2 * TCH * DHID * (int)sizeof(float));
    intra_kernel<<<BSZ * CCH, 256, 2 * TCH * DHID * sizeof(float)>>>(un, kc, y, D_skip, yh, yl);

    // 10) gv = (y @ W_uc^T) * v  (bf16x3) -> split fp16
    tgemm<EPI_MULSPLIT, 0><<<dim3(DGATE / 128, MROWS / 128, 1), 256, TG_SMEM>>>(
        DHID, (const uint16_t*)yh, (const uint16_t*)yl, DHID, 0, 0,
        (const uint16_t*)Wuch, (const uint16_t*)Wucl, DHID, 0, 0,
        v, DGATE, 0, 0, 1, nullptr, nullptr, nullptr, gvh, gvl);

    // 11) out = gv @ W_o^T + b_o + x  (fp16x2)
    tgemm<EPI_FINAL, 1><<<dim3(DIN / 128, MROWS / 128, 1), 256, TG_SMEM>>>(
        DGATE, (const uint16_t*)gvh, (const uint16_t*)gvl, DGATE, 0, 0,
        (const uint16_t*)Wo16, (const uint16_t*)Wo16, DGATE, 0, 0,
        out, DIN, 0, 0, 1, b_o, x, nullptr, nullptr, nullptr);
}

// round 9
// speedup vs baseline: 3.4255x; 1.0180x over previous
#include <cuda_runtime.h>
#include <cuda_fp16.h>
#include <cstdint>
#include <math.h>

// Problem dims
#define BSZ   4
#define LSEQ  8192
#define DIN   512
#define DGATE 2048
#define DHID  128
#define DST   512
#define TCH   128
#define CCH   64
#define MROWS (BSZ*LSEQ)   // 32768
#define NCAT  (DGATE + DHID)   // 2176 fused v+u columns

// ---------------- scratch (static device globals; no runtime alloc) --------
__device__ float g_v   [(size_t)MROWS*DGATE];
__device__ float g_un  [(size_t)MROWS*DHID];
__device__ float g_y   [(size_t)MROWS*DHID];
__device__ float g_Zc  [(size_t)BSZ*CCH*DHID*1024];   // concat [Zre|Zim]
__device__ float g_abar_re [DST];
__device__ float g_abar_im [DST];
__device__ float g_cre     [DHID*DST];
__device__ float g_cim     [DHID*DST];
__device__ float g_kc      [TCH*DHID];
// fp16 operands (hi/lo splits where needed)
__device__ __half g_xnh [(size_t)MROWS*DIN];
__device__ __half g_xnl [(size_t)MROWS*DIN];
__device__ __half g_gvh [(size_t)MROWS*DGATE];
__device__ __half g_gvl [(size_t)MROWS*DGATE];
__device__ __half g_unTh[(size_t)BSZ*DHID*LSEQ];
__device__ __half g_unTl[(size_t)BSZ*DHID*LSEQ];
__device__ __half g_yh  [(size_t)MROWS*DHID];
__device__ __half g_yl  [(size_t)MROWS*DHID];
__device__ __half g_Pch [(size_t)BSZ*CCH*DHID*1024];  // concat [Pre|Pim] hi
__device__ __half g_Pcl [(size_t)BSZ*CCH*DHID*1024];  // lo
__device__ __half g_Wcat16[(size_t)NCAT*DIN];         // [Wv; Wu]
__device__ __half g_Wo16  [(size_t)DIN*DGATE];
__device__ __half g_Wuc16 [(size_t)DGATE*DHID];
__device__ __half g_ArCh [1024*TCH], g_ArCl[1024*TCH];// concat [ArevT_re; ArevT_im] split
__device__ __half g_AhCh [TCH*1024], g_AhCl[TCH*1024];// concat [AhR | -AhI] split

// ---------------- helpers ---------------------------------------------------
__device__ __forceinline__ float gelu_exact(float x) {
    return 0.5f * x * (1.0f + erff(x * 0.70710678118654752440f));
}
__device__ __forceinline__ uint32_t smem_u32(const void* p) {
    uint32_t a;
    asm("{ .reg .u64 t; cvta.to.shared.u64 t, %1; cvt.u32.u64 %0, t; }"
        : "=r"(a) : "l"(p));
    return a;
}
__device__ __forceinline__ void ldm_x4(uint32_t* r, uint32_t addr) {
    asm volatile("ldmatrix.sync.aligned.m8n8.x4.shared.b16 {%0,%1,%2,%3}, [%4];"
        : "=r"(r[0]), "=r"(r[1]), "=r"(r[2]), "=r"(r[3]) : "r"(addr));
}
__device__ __forceinline__ void mma_f16(float* d, const uint32_t* a, const uint32_t* b) {
    asm volatile(
        "mma.sync.aligned.m16n8k16.row.col.f32.f16.f16.f32 "
        "{%0,%1,%2,%3}, {%4,%5,%6,%7}, {%8,%9}, {%0,%1,%2,%3};"
        : "+f"(d[0]), "+f"(d[1]), "+f"(d[2]), "+f"(d[3])
        : "r"(a[0]), "r"(a[1]), "r"(a[2]), "r"(a[3]), "r"(b[0]), "r"(b[1]));
}
__device__ __forceinline__ void cpasync16(uint32_t dst, const void* src) {
    asm volatile("cp.async.cg.shared.global [%0], [%1], 16;" :: "r"(dst), "l"(src));
}

enum { EPI_STORE = 0, EPI_GELU2 = 1, EPI_FINAL = 4, EPI_MULSPLIT = 5 };

#define ROWB    80
#define BUFB    (128 * ROWB)     // 10240
// MODE 0 (3-term): 4 buffers/stage, 2 stages -> 81920 B
// MODE 1 (2-term): 3 buffers/stage, 3 stages -> 92160 B
#define SMEM_M0 (2 * 4 * BUFB)
#define SMEM_M1 (3 * 3 * BUFB)

// ---------------- fp16 HMMA GEMM, cp.async multi-stage pipeline -------------
// C = A(MxK) * B(NxK)^T.
// MODE 0: A hi/lo + B hi/lo, 3 MMAs (AhiBhi + AhiBlo + AloBhi), 2 stages.
// MODE 1: A hi/lo + B single, 2 MMAs, 3 stages.
// 128x128 CTA tile, 8 warps (warp tile 32x64), K chunks of 32.
template <int EPI, int MODE>
__global__ __launch_bounds__(256, 2)
void tgemm(int K,
           const __half* __restrict__ Ah, const __half* __restrict__ Al,
           int lda, long long sAb, long long sAc,
           const __half* __restrict__ Bh, const __half* __restrict__ Bl,
           int ldb, long long sBb, long long sBc,
           float* __restrict__ C, int ldc, long long sCb, long long sCc,
           int CB,
           const float* __restrict__ bias, const float* __restrict__ resid,
           float* __restrict__ C2,
           __half* __restrict__ Oh, __half* __restrict__ Ol)
{
    constexpr int NBUF = (MODE == 0) ? 4 : 3;
    constexpr int NST  = (MODE == 0) ? 2 : 3;
    constexpr int STB  = NBUF * BUFB;

    extern __shared__ __align__(16) char smem[];
    const uint32_t sbase = smem_u32(smem);

    const int tid  = threadIdx.x;
    const int wid  = tid >> 5;
    const int lane = tid & 31;
    const int wm   = wid & 3;
    const int wn   = wid >> 2;

    const int zb = blockIdx.z / CB, zc = blockIdx.z % CB;
    Ah += (size_t)zb * sAb + (size_t)zc * sAc;
    Al += (size_t)zb * sAb + (size_t)zc * sAc;
    Bh += (size_t)zb * sBb + (size_t)zc * sBc;
    if (MODE == 0) Bl += (size_t)zb * sBb + (size_t)zc * sBc;
    C  += (size_t)zb * sCb + (size_t)zc * sCc;
    const int row0 = blockIdx.y * 128;
    const int col0 = blockIdx.x * 128;

    const int lrow = (tid >> 2) & 63;
    const int lc16 = tid & 3;
    const uint32_t sdst0 = (uint32_t)(lrow * ROWB + lc16 * 16);

    float acc[2][8][4];
#pragma unroll
    for (int i = 0; i < 2; i++)
#pragma unroll
        for (int j = 0; j < 8; j++)
#pragma unroll
            for (int k = 0; k < 4; k++) acc[i][j][k] = 0.f;

    const uint32_t aOff = (uint32_t)((wm * 32 + (lane & 15)) * ROWB + ((lane & 16) ? 16 : 0));
    const uint32_t bOff = (uint32_t)(2 * BUFB +
        (wn * 64 + (lane & 7) + ((lane & 16) ? 8 : 0)) * ROWB + ((lane & 8) ? 16 : 0));

    const int nchunk = K >> 5;

    auto issue = [&](int st, int k0) {
        const uint32_t sb = sbase + st * STB;
#pragma unroll
        for (int i = 0; i < 2 * NBUF; i++) {
            const int buf  = i >> 1;                 // 0:Ahi 1:Alo 2:Bhi 3:Blo
            const int row  = (i & 1) * 64 + lrow;
            const int eoff = k0 + lc16 * 8;
            const __half* src;
            if      (buf == 0) src = Ah + (size_t)(row0 + row) * lda + eoff;
            else if (buf == 1) src = Al + (size_t)(row0 + row) * lda + eoff;
            else if (buf == 2) src = Bh + (size_t)(col0 + row) * ldb + eoff;
            else               src = Bl + (size_t)(col0 + row) * ldb + eoff;
            cpasync16(sb + buf * BUFB + (i & 1) * (64 * ROWB) + sdst0, src);
        }
        asm volatile("cp.async.commit_group;" ::: "memory");
    };

    // prologue: NST-1 stages in flight
#pragma unroll
    for (int s = 0; s < NST - 1; s++)
        if (s < nchunk) issue(s, s << 5);

    for (int c = 0; c < nchunk; c++) {
        if (NST == 2) asm volatile("cp.async.wait_group 0;" ::: "memory");
        else          asm volatile("cp.async.wait_group 1;" ::: "memory");
        __syncthreads();
        if (c + NST - 1 < nchunk)
            issue((c + NST - 1) % NST, (c + NST - 1) << 5);
        else if (NST > 2)
            // tail: keep group accounting correct so wait_group 1 actually
            // waits on the final real group (empty groups are cheap)
            asm volatile("cp.async.commit_group;" ::: "memory");

        const uint32_t sb = sbase + (c % NST) * STB;
#pragma unroll
        for (int k16 = 0; k16 < 2; k16++) {
            uint32_t ahi[2][4], alo[2][4];
#pragma unroll
            for (int mt = 0; mt < 2; mt++) {
                const uint32_t aa = sb + aOff + mt * (16 * ROWB) + k16 * 32;
                ldm_x4(ahi[mt], aa);
                ldm_x4(alo[mt], aa + BUFB);
            }
#pragma unroll
            for (int p = 0; p < 4; p++) {
                const uint32_t ba = sb + bOff + p * (16 * ROWB) + k16 * 32;
                uint32_t bhi[4];
                ldm_x4(bhi, ba);
                uint32_t blo[4];
                if (MODE == 0) ldm_x4(blo, ba + BUFB);
#pragma unroll
                for (int mt = 0; mt < 2; mt++) {
#pragma unroll
                    for (int hh = 0; hh < 2; hh++) {
                        float* d = acc[mt][p * 2 + hh];
                        mma_f16(d, ahi[mt], &bhi[hh * 2]);
                        if (MODE == 0) mma_f16(d, ahi[mt], &blo[hh * 2]);
                        mma_f16(d, alo[mt], &bhi[hh * 2]);
                    }
                }
            }
        }
    }

    // ---- epilogue ----
    const int qrow = lane >> 2, qcol = (lane & 3) * 2;
#pragma unroll
    for (int mt = 0; mt < 2; mt++) {
#pragma unroll
        for (int nt = 0; nt < 8; nt++) {
            const int r0r = row0 + wm * 32 + mt * 16 + qrow;
            const int cc  = col0 + wn * 64 + nt * 8 + qcol;
            float* d = acc[mt][nt];
#pragma unroll
            for (int h = 0; h < 2; h++) {
                const int rr = r0r + h * 8;
                const size_t idx = (size_t)rr * ldc + cc;
                float2 o = make_float2(d[h * 2 + 0], d[h * 2 + 1]);
                if (EPI == EPI_GELU2) {
                    o.x = gelu_exact(o.x); o.y = gelu_exact(o.y);
                    if (cc < DGATE) *(float2*)(C + idx) = o;
                    else *(float2*)(C2 + (size_t)rr * DHID + (cc - DGATE)) = o;
                } else if (EPI == EPI_FINAL) {
                    const float2 bb = *(const float2*)(bias + cc);
                    const float2 rr2 = *(const float2*)(resid + idx);
                    o.x += bb.x + rr2.x; o.y += bb.y + rr2.y;
                    *(float2*)(C + idx) = o;
                } else if (EPI == EPI_MULSPLIT) {
                    const float2 q = *(const float2*)(C + idx);   // gate v (fp32)
                    o.x *= q.x; o.y *= q.y;
                    __half2 hh2 = __floats2half2_rn(o.x, o.y);
                    float lx = o.x - __low2float(hh2);
                    float ly = o.y - __high2float(hh2);
                    *(__half2*)(Oh + idx) = hh2;
                    *(__half2*)(Ol + idx) = __floats2half2_rn(lx, ly);
                } else {  // EPI_STORE
                    *(float2*)(C + idx) = o;
                }
            }
        }
    }
}

// ---------------- layernorm over 512 -> split fp16 --------------------------
__global__ void ln512(const float* __restrict__ x, const float* __restrict__ g,
                      const float* __restrict__ b,
                      __half* __restrict__ xnh, __half* __restrict__ xnl)
{
    const int row = blockIdx.x, tid = threadIdx.x;  // 128 threads
    float4 v = ((const float4*)(x + (size_t)row * 512))[tid];
    float s  = v.x + v.y + v.z + v.w;
    float sq = v.x * v.x + v.y * v.y + v.z * v.z + v.w * v.w;
#pragma unroll
    for (int o = 16; o; o >>= 1) {
        s  += __shfl_xor_sync(0xffffffffu, s, o);
        sq += __shfl_xor_sync(0xffffffffu, sq, o);
    }
    __shared__ float ss[4], ssq[4];
    if ((tid & 31) == 0) { ss[tid >> 5] = s; ssq[tid >> 5] = sq; }
    __syncthreads();
    s  = ss[0] + ss[1] + ss[2] + ss[3];
    sq = ssq[0] + ssq[1] + ssq[2] + ssq[3];
    const float mean = s * (1.f / 512.f);
    const float var  = sq * (1.f / 512.f) - mean * mean;
    const float rs   = rsqrtf(var + 1e-5f);
    float4 gv = ((const float4*)g)[tid], bv = ((const float4*)b)[tid];
    float4 o4;
    o4.x = (v.x - mean) * rs * gv.x + bv.x;
    o4.y = (v.y - mean) * rs * gv.y + bv.y;
    o4.z = (v.z - mean) * rs * gv.z + bv.z;
    o4.w = (v.w - mean) * rs * gv.w + bv.w;
    __half2 h01 = __floats2half2_rn(o4.x, o4.y);
    __half2 h23 = __floats2half2_rn(o4.z, o4.w);
    __half2 l01 = __floats2half2_rn(o4.x - __low2float(h01), o4.y - __high2float(h01));
    __half2 l23 = __floats2half2_rn(o4.z - __low2float(h23), o4.w - __high2float(h23));
    uint2 hv, lv;
    hv.x = *(uint32_t*)&h01; hv.y = *(uint32_t*)&h23;
    lv.x = *(uint32_t*)&l01; lv.y = *(uint32_t*)&l23;
    *(uint2*)(xnh + (size_t)row * 512 + tid * 4) = hv;
    *(uint2*)(xnl + (size_t)row * 512 + tid * 4) = lv;
}

// ---------------- layernorm over 128: un fp32 in place + unT split fp16 -----
__global__ void ln128(float* __restrict__ u, __half* __restrict__ uTh,
                      __half* __restrict__ uTl,
                      const float* __restrict__ g, const float* __restrict__ b)
{
    const int warp = threadIdx.x >> 5, lane = threadIdx.x & 31;
    const int row  = blockIdx.x * 8 + warp;
    float4 v = ((const float4*)(u + (size_t)row * 128))[lane];
    float s  = v.x + v.y + v.z + v.w;
    float sq = v.x * v.x + v.y * v.y + v.z * v.z + v.w * v.w;
#pragma unroll
    for (int o = 16; o; o >>= 1) {
        s  += __shfl_xor_sync(0xffffffffu, s, o);
        sq += __shfl_xor_sync(0xffffffffu, sq, o);
    }
    const float mean = s * (1.f / 128.f);
    const float var  = sq * (1.f / 128.f) - mean * mean;
    const float rs   = rsqrtf(var + 1e-5f);
    float4 gv = ((const float4*)g)[lane], bv = ((const float4*)b)[lane];
    float4 o4;
    o4.x = (v.x - mean) * rs * gv.x + bv.x;
    o4.y = (v.y - mean) * rs * gv.y + bv.y;
    o4.z = (v.z - mean) * rs * gv.z + bv.z;
    o4.w = (v.w - mean) * rs * gv.w + bv.w;
    ((float4*)(u + (size_t)row * 128))[lane] = o4;
    const int bb = row >> 13, l = row & 8191;
    const size_t tbase = (size_t)bb * 128 * 8192 + l;
    const int h = lane * 4;
    float vals[4] = {o4.x, o4.y, o4.z, o4.w};
#pragma unroll
    for (int k = 0; k < 4; k++) {
        __half hh = __float2half_rn(vals[k]);
        uTh[tbase + (size_t)(h + k) * 8192] = hh;
        uTl[tbase + (size_t)(h + k) * 8192] = __float2half_rn(vals[k] - __half2float(hh));
    }
}

// ---------------- DSS tables (split fp16 tables) -----------------------------
__global__ void dss_tables(const float* __restrict__ lam_re, const float* __restrict__ lam_im,
                           const float* __restrict__ C_re, const float* __restrict__ C_im,
                           __half* ArCh, __half* ArCl, __half* AhCh, __half* AhCl,
                           float* __restrict__ abar_re, float* __restrict__ abar_im,
                           float* __restrict__ cre, float* __restrict__ cim)
{
    const int n = blockIdx.x * 128 + threadIdx.x;
    if (n >= DST) return;
    const float lre = -expf(lam_re[n]);
    const float lim =  expf(lam_im[n]);
    const float mag = expf(lre);
    const float er = mag * cosf(lim), ei = mag * sinf(lim);
    const float den = lre * lre + lim * lim;
    const float nr = er - 1.f, ni = ei;
    const float wr = (nr * lre + ni * lim) / den;
    const float wi = (ni * lre - nr * lim) / den;
    for (int h = 0; h < DHID; h++) {
        const float a = C_re[h * DST + n], b = C_im[h * DST + n];
        cre[h * DST + n] = a * wr - b * wi;
        cim[h * DST + n] = a * wi + b * wr;
    }
    for (int t = 0; t < TCH; t++) {
        const float x1 = (float)(TCH - 1 - t);
        const float m1 = expf(x1 * lre);
        const float vr = m1 * cosf(x1 * lim), vi = m1 * sinf(x1 * lim);
        __half hr = __float2half_rn(vr);
        ArCh[n * TCH + t] = hr;
        ArCl[n * TCH + t] = __float2half_rn(vr - __half2float(hr));
        __half hi = __float2half_rn(vi);
        ArCh[(512 + n) * TCH + t] = hi;
        ArCl[(512 + n) * TCH + t] = __float2half_rn(vi - __half2float(hi));
        const float x2 = (float)(t + 1);
        const float m2 = expf(x2 * lre);
        const float wr2 = m2 * cosf(x2 * lim);
        const float wi2 = -m2 * sinf(x2 * lim);     // negated for [AhR | -AhI]
        __half h2 = __float2half_rn(wr2);
        AhCh[t * 1024 + n] = h2;
        AhCl[t * 1024 + n] = __float2half_rn(wr2 - __half2float(h2));
        __half h3 = __float2half_rn(wi2);
        AhCh[t * 1024 + 512 + n] = h3;
        AhCl[t * 1024 + 512 + n] = __float2half_rn(wi2 - __half2float(h3));
    }
    const float m3 = expf((float)TCH * lre);
    abar_re[n] = m3 * cosf((float)TCH * lim);
    abar_im[n] = m3 * sinf((float)TCH * lim);
}

// kern_chunk[d,h] = Re( sum_n c[h,n] exp(d*lam_n) )
__global__ void kernchunk(const float* __restrict__ lam_re, const float* __restrict__ lam_im,
                          const float* __restrict__ cre, const float* __restrict__ cim,
                          float* __restrict__ kc)
{
    const int d = blockIdx.x, h = threadIdx.x;   // <<<128,128>>>
    __shared__ float er[DST], ei[DST];
    for (int n = h; n < DST; n += 128) {
        const float lre = -expf(lam_re[n]);
        const float lim =  expf(lam_im[n]);
        const float m = expf((float)d * lre);
        er[n] = m * cosf((float)d * lim);
        ei[n] = m * sinf((float)d * lim);
    }
    __syncthreads();
    float s = 0.f;
    for (int n = 0; n < DST; n++)
        s += cre[h * DST + n] * er[n] - cim[h * DST + n] * ei[n];
    kc[d * DHID + h] = s;
}

// ---------------- chunk scan: concat Z fp32 in, concat split-fp16 P out -----
__global__ void scan_kernel(const float* __restrict__ Zc,
                            __half* __restrict__ Pch, __half* __restrict__ Pcl,
                            const float* __restrict__ cre, const float* __restrict__ cim,
                            const float* __restrict__ abr, const float* __restrict__ abi)
{
    const int t = blockIdx.x * 256 + threadIdx.x;   // [0, 262144)
    const int n = t & 511, h = (t >> 9) & 127, b = t >> 16;
    const float ar = abr[n], ai = abi[n];
    const float kr = cre[h * DST + n], ki = cim[h * DST + n];
    float Sr = 0.f, Si = 0.f;
    const size_t stride = (size_t)DHID * 1024;
    size_t idx = ((size_t)b * CCH * DHID + h) * 1024 + n;
    for (int c = 0; c < CCH; c++) {
        const float zr = Zc[idx], zi = Zc[idx + 512];
        const float pr = kr * Sr - ki * Si;
        const float pi = kr * Si + ki * Sr;
        __half ph = __float2half_rn(pr);
        Pch[idx] = ph; Pcl[idx] = __float2half_rn(pr - __half2float(ph));
        __half qh = __float2half_rn(pi);
        Pch[idx + 512] = qh; Pcl[idx + 512] = __float2half_rn(pi - __half2float(qh));
        const float t1 = ar * Sr - ai * Si + zr;
        Si = ar * Si + ai * Sr + zi;
        Sr = t1;
        idx += stride;
    }
}

// ---------------- intra-chunk conv + skip; writes split fp16 y ---------------
__global__ void intra_kernel(const float* __restrict__ un, const float* __restrict__ kc,
                             const float* __restrict__ y, const float* __restrict__ Ds,
                             __half* __restrict__ yh, __half* __restrict__ yl)
{
    extern __shared__ float sm[];
    float* Uc = sm;
    float* Kc = sm + TCH * DHID;
    const size_t base = (size_t)blockIdx.x * TCH * DHID;
    for (int i = threadIdx.x; i < TCH * DHID / 4; i += 256) {
        ((float4*)Uc)[i] = ((const float4*)(un + base))[i];
        ((float4*)Kc)[i] = ((const float4*)kc)[i];
    }
    __syncthreads();
    for (int e = threadIdx.x; e < TCH * DHID; e += 256) {
        const int dt = e >> 7, h = e & 127;
        float s = Uc[dt * DHID + h] * Ds[h] + y[base + e];
        for (int j = 0; j <= dt; j++)
            s = fmaf(Kc[(dt - j) * DHID + h], Uc[j * DHID + h], s);
        __half hh = __float2half_rn(s);
        yh[base + e] = hh;
        yl[base + e] = __float2half_rn(s - __half2float(hh));
    }
}

// ---------------- fp32 -> fp16 round ----------------------------------------
__global__ void fround16(const float* __restrict__ s, __half* __restrict__ d, int n)
{
    const int i = blockIdx.x * 256 + threadIdx.x;
    if (i < n) d[i] = __float2half_rn(s[i]);
}

// ---------------- launch ----------------------------------------------------
extern "C" void kernel_launch(void* const* d_in, const int* in_sizes, int n_in,
                              void* d_out, int out_size)
{
    const float* x      = (const float*)d_in[0];
    const float* norm_g = (const float*)d_in[1];
    const float* norm_b = (const float*)d_in[2];
    const float* W_v    = (const float*)d_in[3];
    const float* W_u    = (const float*)d_in[4];
    const float* W_uc   = (const float*)d_in[5];
    const float* W_o    = (const float*)d_in[6];
    const float* b_o    = (const float*)d_in[7];
    const float* dss_g  = (const float*)d_in[8];
    const float* dss_b  = (const float*)d_in[9];
    const float* lam_re = (const float*)d_in[10];
    const float* lam_im = (const float*)d_in[11];
    const float* C_re   = (const float*)d_in[12];
    const float* C_im   = (const float*)d_in[13];
    const float* D_skip = (const float*)d_in[14];
    float* out = (float*)d_out;

    float *v, *un, *y, *Zc, *abr, *abi, *cre, *cim, *kc;
    __half *xnh, *xnl, *gvh, *gvl, *unTh, *unTl, *yh, *yl, *Pch, *Pcl;
    __half *Wcat16, *Wo16, *Wuc16, *ArCh, *ArCl, *AhCh, *AhCl;
    cudaGetSymbolAddress((void**)&v,   g_v);
    cudaGetSymbolAddress((void**)&un,  g_un);
    cudaGetSymbolAddress((void**)&y,   g_y);
    cudaGetSymbolAddress((void**)&Zc,  g_Zc);
    cudaGetSymbolAddress((void**)&abr, g_abar_re);
    cudaGetSymbolAddress((void**)&abi, g_abar_im);
    cudaGetSymbolAddress((void**)&cre, g_cre);
    cudaGetSymbolAddress((void**)&cim, g_cim);
    cudaGetSymbolAddress((void**)&kc,  g_kc);
    cudaGetSymbolAddress((void**)&xnh, g_xnh);
    cudaGetSymbolAddress((void**)&xnl, g_xnl);
    cudaGetSymbolAddress((void**)&gvh, g_gvh);
    cudaGetSymbolAddress((void**)&gvl, g_gvl);
    cudaGetSymbolAddress((void**)&unTh, g_unTh);
    cudaGetSymbolAddress((void**)&unTl, g_unTl);
    cudaGetSymbolAddress((void**)&yh,  g_yh);
    cudaGetSymbolAddress((void**)&yl,  g_yl);
    cudaGetSymbolAddress((void**)&Pch, g_Pch);
    cudaGetSymbolAddress((void**)&Pcl, g_Pcl);
    cudaGetSymbolAddress((void**)&Wcat16, g_Wcat16);
    cudaGetSymbolAddress((void**)&Wo16, g_Wo16);
    cudaGetSymbolAddress((void**)&Wuc16, g_Wuc16);
    cudaGetSymbolAddress((void**)&ArCh, g_ArCh);
    cudaGetSymbolAddress((void**)&ArCl, g_ArCl);
    cudaGetSymbolAddress((void**)&AhCh, g_AhCh);
    cudaGetSymbolAddress((void**)&AhCl, g_AhCl);

    cudaFuncSetAttribute(tgemm<EPI_GELU2, 1>, cudaFuncAttributeMaxDynamicSharedMemorySize, SMEM_M1);
    cudaFuncSetAttribute(tgemm<EPI_STORE, 0>, cudaFuncAttributeMaxDynamicSharedMemorySize, SMEM_M0);
    cudaFuncSetAttribute(tgemm<EPI_MULSPLIT, 1>, cudaFuncAttributeMaxDynamicSharedMemorySize, SMEM_M1);
    cudaFuncSetAttribute(tgemm<EPI_FINAL, 1>, cudaFuncAttributeMaxDynamicSharedMemorySize, SMEM_M1);

    // 0) prep weights (fp16)
    fround16<<<(DGATE * DIN + 255) / 256, 256>>>(W_v, Wcat16, DGATE * DIN);
    fround16<<<(DHID * DIN + 255) / 256, 256>>>(W_u, Wcat16 + (size_t)DGATE * DIN, DHID * DIN);
    fround16<<<(DIN * DGATE + 255) / 256, 256>>>(W_o, Wo16, DIN * DGATE);
    fround16<<<(DGATE * DHID + 255) / 256, 256>>>(W_uc, Wuc16, DGATE * DHID);

    // 1) xn = LN(x) -> split fp16
    ln512<<<MROWS, 128>>>(x, norm_g, norm_b, xnh, xnl);

    // 2+3) [v | u] = gelu(xn @ [Wv; Wu]^T)  fused, fp16x2, N=2176
    tgemm<EPI_GELU2, 1><<<dim3(NCAT / 128, MROWS / 128, 1), 256, SMEM_M1>>>(
        DIN, xnh, xnl, DIN, 0, 0, Wcat16, nullptr, DIN, 0, 0,
        v, DGATE, 0, 0, 1, nullptr, nullptr, un, nullptr, nullptr);

    // 4) un = LN(u) fp32 in place; unT split fp16
    ln128<<<MROWS / 8, 256>>>(un, unTh, unTl, dss_g, dss_b);

    // 5) DSS tables
    dss_tables<<<DST / 128, 128>>>(lam_re, lam_im, C_re, C_im,
                                   ArCh, ArCl, AhCh, AhCl, abr, abi, cre, cim);
    kernchunk<<<TCH, DHID>>>(lam_re, lam_im, cre, cim, kc);

    // 6) Zc[b,c,h,n2] = sum_t unT[b,h,cT+t] * ArC[n2,t]   (fp16x3)
    tgemm<EPI_STORE, 0><<<dim3(8, 1, BSZ * CCH), 256, SMEM_M0>>>(
        TCH, unTh, unTl, LSEQ, (long long)DHID * LSEQ, TCH,
        ArCh, ArCl, TCH, 0, 0,
        Zc, 1024, (long long)CCH * DHID * 1024, (long long)DHID * 1024,
        CCH, nullptr, nullptr, nullptr, nullptr, nullptr);

    // 7) scan across chunks; P = c * S_start, concat [Pre|Pim] split fp16
    scan_kernel<<<(BSZ * DHID * DST) / 256, 256>>>(Zc, Pch, Pcl, cre, cim, abr, abi);

    // 8) y_inter = [AhR | -AhI] @ P^T, single K=1024 GEMM (fp16x3)
    tgemm<EPI_STORE, 0><<<dim3(1, 1, BSZ * CCH), 256, SMEM_M0>>>(
        1024, AhCh, AhCl, 1024, 0, 0,
        Pch, Pcl, 1024, (long long)CCH * DHID * 1024, (long long)DHID * 1024,
        y, DHID, (long long)CCH * TCH * DHID, (long long)TCH * DHID,
        CCH, nullptr, nullptr, nullptr, nullptr, nullptr);

    // 9) y += intra conv + skip; write split fp16 y
    cudaFuncSetAttribute(intra_kernel, cudaFuncAttributeMaxDynamicSharedMemorySize,
                         2 * TCH * DHID * (int)sizeof(float));
    intra_kernel<<<BSZ * CCH, 256, 2 * TCH * DHID * sizeof(float)>>>(un, kc, y, D_skip, yh, yl);

    // 10) gv = (y @ W_uc^T) * v  (fp16x2) -> split fp16
    tgemm<EPI_MULSPLIT, 1><<<dim3(DGATE / 128, MROWS / 128, 1), 256, SMEM_M1>>>(
        DHID, yh, yl, DHID, 0, 0, Wuc16, nullptr, DHID, 0, 0,
        v, DGATE, 0, 0, 1, nullptr, nullptr, nullptr, gvh, gvl);

    // 11) out = gv @ W_o^T + b_o + x  (fp16x2)
    tgemm<EPI_FINAL, 1><<<dim3(DIN / 128, MROWS / 128, 1), 256, SMEM_M1>>>(
        DGATE, gvh, gvl, DGATE, 0, 0, Wo16, nullptr, DGATE, 0, 0,
        out, DIN, 0, 0, 1, b_o, x, nullptr, nullptr, nullptr);
}